// round 1
// baseline (speedup 1.0000x reference)
#include <cuda_runtime.h>
#include <math.h>

#define NP 65536
#define CDIM 180
#define NHEADS 6
#define HD 30
#define HID 720

// ---------------- scratch (device globals; no allocations) ----------------
__device__ float g_xn[NP * CDIM];
__device__ float g_xnT[CDIM * NP];
__device__ float g_xw[NP * CDIM];
__device__ float g_qkv[NP * 3 * CDIM];
__device__ float g_attn[NP * CDIM];
__device__ float g_proj[NP * CDIM];
__device__ float g_y1T[60 * NP];
__device__ float g_y2[NP * CDIM];
__device__ float g_rpb[NHEADS * 256 * 256];
__device__ float g_casum[CDIM];
__device__ float g_ca[CDIM];
__device__ float g_x1[NP * CDIM];
__device__ float g_xm[NP * CDIM];
__device__ float g_mb[NP * HID];

__device__ __forceinline__ float gelu_f(float x) {
    return 0.5f * x * (1.0f + erff(x * 0.70710678118654752f));
}

__device__ __forceinline__ float warp_sum(float v) {
    for (int o = 16; o > 0; o >>= 1) v += __shfl_xor_sync(0xffffffffu, v, o);
    return v;
}

// ---------------- LayerNorm (one warp per token) ----------------
__global__ void ln_kernel(const float* __restrict__ x, const float* __restrict__ g,
                          const float* __restrict__ b, float* __restrict__ out) {
    int p = blockIdx.x * 8 + (threadIdx.x >> 5);
    int lane = threadIdx.x & 31;
    const float* xr = x + p * CDIM;
    float v[6];
    float s = 0.f;
#pragma unroll
    for (int k = 0; k < 6; k++) {
        int c = k * 32 + lane;
        v[k] = (c < CDIM) ? xr[c] : 0.f;
        s += v[k];
    }
    s = warp_sum(s);
    float mu = s * (1.0f / CDIM);
    float sq = 0.f;
#pragma unroll
    for (int k = 0; k < 6; k++) {
        int c = k * 32 + lane;
        if (c < CDIM) { float d = v[k] - mu; sq += d * d; }
    }
    sq = warp_sum(sq);
    float rstd = rsqrtf(sq * (1.0f / CDIM) + 1e-5f);
    float* orow = out + p * CDIM;
#pragma unroll
    for (int k = 0; k < 6; k++) {
        int c = k * 32 + lane;
        if (c < CDIM) orow[c] = (v[k] - mu) * rstd * g[c] + b[c];
    }
}

// ---------------- transpose [NP][C] -> [C][NP] ----------------
__global__ void transpose_kernel(const float* __restrict__ in, float* __restrict__ out) {
    __shared__ float tile[32][33];
    int c0 = blockIdx.x * 32;
    int p0 = blockIdx.y * 32;
    int tx = threadIdx.x, ty = threadIdx.y;
    for (int i = ty; i < 32; i += 8) {
        int c = c0 + tx;
        tile[i][tx] = (c < CDIM) ? in[(p0 + i) * CDIM + c] : 0.f;
    }
    __syncthreads();
    for (int i = ty; i < 32; i += 8) {
        int c = c0 + i;
        if (c < CDIM) out[c * NP + p0 + tx] = tile[tx][i];
    }
}

// ---------------- roll(-8,-8) + window partition gather ----------------
__global__ void gather_kernel(const float* __restrict__ xn, float* __restrict__ xw) {
    int widx = blockIdx.x;
    int c = threadIdx.x;
    if (c >= CDIM) return;
    int win = widx >> 8, tok = widx & 255;
    int hs = ((win >> 4) << 4) + (tok >> 4);
    int ws2 = ((win & 15) << 4) + (tok & 15);
    int hr = (hs + 8) & 255;
    int wr = (ws2 + 8) & 255;
    xw[widx * CDIM + c] = xn[(hr * 256 + wr) * CDIM + c];
}

// ---------------- relative position bias matrix ----------------
__global__ void rpb_kernel(const int* __restrict__ rpi, const float* __restrict__ table,
                           float* __restrict__ rpb) {
    int idx = blockIdx.x * 256 + threadIdx.x;   // over 65536 (q,k) pairs
    int r = rpi[idx];
#pragma unroll
    for (int h = 0; h < NHEADS; h++) rpb[h * 65536 + idx] = table[r * NHEADS + h];
}

// ---------------- generic tiled fp32 GEMM with epilogues ----------------
// C[M,N] = A[M,K] @ B[K,N] + bias ; EPI: 0 = bias, 1 = bias+gelu, 2 = bias+residual
template <int EPI>
__global__ void gemm_kernel(const float* __restrict__ A, const float* __restrict__ B,
                            const float* __restrict__ bias, const float* __restrict__ res,
                            float* __restrict__ C, int M, int N, int K) {
    __shared__ float As[16][64];
    __shared__ float Bs[16][64];
    int m0 = blockIdx.y * 64;
    int n0 = blockIdx.x * 64;
    int tid = threadIdx.y * 16 + threadIdx.x;
    int am = tid >> 2, ak = (tid & 3) * 4;
    int bk = tid >> 4, bn = (tid & 15) * 4;
    float acc[4][4] = {};
    for (int k0 = 0; k0 < K; k0 += 16) {
        // A tile
        {
            int kk = k0 + ak;
            int row = m0 + am;
            float4 v = make_float4(0.f, 0.f, 0.f, 0.f);
            if (kk + 3 < K) v = *(const float4*)&A[row * K + kk];
            else {
                float t0 = (kk + 0 < K) ? A[row * K + kk + 0] : 0.f;
                float t1 = (kk + 1 < K) ? A[row * K + kk + 1] : 0.f;
                float t2 = (kk + 2 < K) ? A[row * K + kk + 2] : 0.f;
                float t3 = (kk + 3 < K) ? A[row * K + kk + 3] : 0.f;
                v = make_float4(t0, t1, t2, t3);
            }
            As[ak + 0][am] = v.x; As[ak + 1][am] = v.y;
            As[ak + 2][am] = v.z; As[ak + 3][am] = v.w;
        }
        // B tile
        {
            int kk = k0 + bk;
            int col = n0 + bn;
            float4 v = make_float4(0.f, 0.f, 0.f, 0.f);
            if (kk < K) {
                if (col + 3 < N) v = *(const float4*)&B[kk * N + col];
                else {
                    float t0 = (col + 0 < N) ? B[kk * N + col + 0] : 0.f;
                    float t1 = (col + 1 < N) ? B[kk * N + col + 1] : 0.f;
                    float t2 = (col + 2 < N) ? B[kk * N + col + 2] : 0.f;
                    float t3 = (col + 3 < N) ? B[kk * N + col + 3] : 0.f;
                    v = make_float4(t0, t1, t2, t3);
                }
            }
            *(float4*)&Bs[bk][bn] = v;
        }
        __syncthreads();
#pragma unroll
        for (int kk = 0; kk < 16; kk++) {
            float4 a4 = *(const float4*)&As[kk][threadIdx.y * 4];
            float4 b4 = *(const float4*)&Bs[kk][threadIdx.x * 4];
            acc[0][0] += a4.x * b4.x; acc[0][1] += a4.x * b4.y; acc[0][2] += a4.x * b4.z; acc[0][3] += a4.x * b4.w;
            acc[1][0] += a4.y * b4.x; acc[1][1] += a4.y * b4.y; acc[1][2] += a4.y * b4.z; acc[1][3] += a4.y * b4.w;
            acc[2][0] += a4.z * b4.x; acc[2][1] += a4.z * b4.y; acc[2][2] += a4.z * b4.z; acc[2][3] += a4.z * b4.w;
            acc[3][0] += a4.w * b4.x; acc[3][1] += a4.w * b4.y; acc[3][2] += a4.w * b4.z; acc[3][3] += a4.w * b4.w;
        }
        __syncthreads();
    }
    int mbase = m0 + threadIdx.y * 4;
    int nbase = n0 + threadIdx.x * 4;
#pragma unroll
    for (int i = 0; i < 4; i++) {
#pragma unroll
        for (int j = 0; j < 4; j++) {
            int n = nbase + j;
            if (n >= N) continue;
            float v = acc[i][j] + bias[n];
            if (EPI == 1) v = gelu_f(v);
            if (EPI == 2) v += res[(mbase + i) * N + n];
            C[(mbase + i) * N + n] = v;
        }
    }
}

// ---------------- conv1: [C=180][NP] -> gelu -> [60][NP] ----------------
__global__ void conv1_kernel(const float* __restrict__ in, const float* __restrict__ w,
                             const float* __restrict__ bias, float* __restrict__ out) {
    __shared__ float As[16][64];
    __shared__ float Bs[16][64];
    int tile = blockIdx.x;
    int row = tile >> 2, seg = tile & 3;
    int cb = seg * 64;
    int pbase = row * 256 + cb;
    int tid = threadIdx.y * 16 + threadIdx.x;
    int lkk = tid >> 4;
    int lp4 = (tid & 15) * 4;
    float acc[4][4] = {};
    for (int t = 0; t < 9; t++) {
        int dy = t / 3 - 1, dx = t % 3 - 1;
        int r2 = row + dy;
        bool rok = ((unsigned)r2 < 256u);
        for (int icb = 0; icb < 180; icb += 16) {
            int ic = icb + lkk;
#pragma unroll
            for (int q = 0; q < 4; q++) {
                int px = lp4 + q;
                int col = cb + px + dx;
                float v = 0.f;
                if (rok && (unsigned)col < 256u && ic < 180)
                    v = in[ic * NP + r2 * 256 + col];
                As[lkk][px] = v;
            }
#pragma unroll
            for (int q = 0; q < 4; q++) {
                int oc = lp4 + q;
                float v = 0.f;
                if (oc < 60 && ic < 180) v = w[(oc * 180 + ic) * 9 + t];
                Bs[lkk][oc] = v;
            }
            __syncthreads();
#pragma unroll
            for (int kk = 0; kk < 16; kk++) {
                float4 a4 = *(const float4*)&As[kk][threadIdx.y * 4];
                float4 b4 = *(const float4*)&Bs[kk][threadIdx.x * 4];
                acc[0][0] += a4.x * b4.x; acc[0][1] += a4.x * b4.y; acc[0][2] += a4.x * b4.z; acc[0][3] += a4.x * b4.w;
                acc[1][0] += a4.y * b4.x; acc[1][1] += a4.y * b4.y; acc[1][2] += a4.y * b4.z; acc[1][3] += a4.y * b4.w;
                acc[2][0] += a4.z * b4.x; acc[2][1] += a4.z * b4.y; acc[2][2] += a4.z * b4.z; acc[2][3] += a4.z * b4.w;
                acc[3][0] += a4.w * b4.x; acc[3][1] += a4.w * b4.y; acc[3][2] += a4.w * b4.z; acc[3][3] += a4.w * b4.w;
            }
            __syncthreads();
        }
    }
    int py = threadIdx.y * 4;
#pragma unroll
    for (int j = 0; j < 4; j++) {
        int oc = threadIdx.x * 4 + j;
        if (oc < 60) {
            float b0 = bias[oc];
            float4 v;
            v.x = gelu_f(acc[0][j] + b0);
            v.y = gelu_f(acc[1][j] + b0);
            v.z = gelu_f(acc[2][j] + b0);
            v.w = gelu_f(acc[3][j] + b0);
            *(float4*)&out[oc * NP + pbase + py] = v;
        }
    }
}

// ---------------- conv2: [60][NP] -> [NP][180] (NHWC out) ----------------
__global__ void conv2_kernel(const float* __restrict__ in, const float* __restrict__ w,
                             const float* __restrict__ bias, float* __restrict__ out) {
    __shared__ float As[16][64];
    __shared__ float Bs[16][64];
    int tile = blockIdx.x;
    int n0 = blockIdx.y * 64;
    int row = tile >> 2, seg = tile & 3;
    int cb = seg * 64;
    int pbase = row * 256 + cb;
    int tid = threadIdx.y * 16 + threadIdx.x;
    int lkk = tid >> 4;
    int lp4 = (tid & 15) * 4;
    float acc[4][4] = {};
    for (int t = 0; t < 9; t++) {
        int dy = t / 3 - 1, dx = t % 3 - 1;
        int r2 = row + dy;
        bool rok = ((unsigned)r2 < 256u);
        for (int icb = 0; icb < 60; icb += 16) {
            int ic = icb + lkk;
#pragma unroll
            for (int q = 0; q < 4; q++) {
                int px = lp4 + q;
                int col = cb + px + dx;
                float v = 0.f;
                if (rok && (unsigned)col < 256u && ic < 60)
                    v = in[ic * NP + r2 * 256 + col];
                As[lkk][px] = v;
            }
#pragma unroll
            for (int q = 0; q < 4; q++) {
                int oc = n0 + lp4 + q;
                float v = 0.f;
                if (oc < 180 && ic < 60) v = w[(oc * 60 + ic) * 9 + t];
                Bs[lkk][lp4 + q] = v;
            }
            __syncthreads();
#pragma unroll
            for (int kk = 0; kk < 16; kk++) {
                float4 a4 = *(const float4*)&As[kk][threadIdx.y * 4];
                float4 b4 = *(const float4*)&Bs[kk][threadIdx.x * 4];
                acc[0][0] += a4.x * b4.x; acc[0][1] += a4.x * b4.y; acc[0][2] += a4.x * b4.z; acc[0][3] += a4.x * b4.w;
                acc[1][0] += a4.y * b4.x; acc[1][1] += a4.y * b4.y; acc[1][2] += a4.y * b4.z; acc[1][3] += a4.y * b4.w;
                acc[2][0] += a4.z * b4.x; acc[2][1] += a4.z * b4.y; acc[2][2] += a4.z * b4.z; acc[2][3] += a4.z * b4.w;
                acc[3][0] += a4.w * b4.x; acc[3][1] += a4.w * b4.y; acc[3][2] += a4.w * b4.z; acc[3][3] += a4.w * b4.w;
            }
            __syncthreads();
        }
    }
    int oc0 = n0 + threadIdx.x * 4;
    if (oc0 < 180) {
        float4 bb = *(const float4*)&bias[oc0];
#pragma unroll
        for (int i = 0; i < 4; i++) {
            int pix = pbase + threadIdx.y * 4 + i;
            float4 v;
            v.x = acc[i][0] + bb.x; v.y = acc[i][1] + bb.y;
            v.z = acc[i][2] + bb.z; v.w = acc[i][3] + bb.w;
            *(float4*)&out[pix * CDIM + oc0] = v;
        }
    }
}

// ---------------- channel-attention pooling ----------------
__global__ void pool_kernel(const float* __restrict__ y2, float* __restrict__ casum) {
    int c = threadIdx.x;
    if (c >= CDIM) return;
    int p0 = blockIdx.x * 256;
    float s = 0.f;
    for (int i = 0; i < 256; i++) s += y2[(p0 + i) * CDIM + c];
    atomicAdd(&casum[c], s);
}

__global__ void ca_kernel(const float* __restrict__ casum,
                          const float* __restrict__ w1, const float* __restrict__ b1,
                          const float* __restrict__ w2, const float* __restrict__ b2,
                          float* __restrict__ ca) {
    __shared__ float mean[CDIM];
    __shared__ float sq[6];
    int t = threadIdx.x;
    if (t < CDIM) mean[t] = casum[t] * (1.0f / NP);
    __syncthreads();
    if (t < 6) {
        float a = b1[t];
        for (int c = 0; c < CDIM; c++) a += mean[c] * w1[t * CDIM + c];
        sq[t] = fmaxf(a, 0.f);
    }
    __syncthreads();
    if (t < CDIM) {
        float a = b2[t];
#pragma unroll
        for (int s = 0; s < 6; s++) a += sq[s] * w2[t * 6 + s];
        ca[t] = 1.0f / (1.0f + __expf(-a));
    }
}

// ---------------- flash attention per (window, head) ----------------
__global__ void __launch_bounds__(256) attn_kernel(const float* __restrict__ qkv,
                                                   const float* __restrict__ rpb,
                                                   const float* __restrict__ mask,
                                                   float* __restrict__ out) {
    int win = blockIdx.x;
    int head = blockIdx.y;
    __shared__ float ks[32][30];
    __shared__ float vs[32][30];
    int qi = threadIdx.x;
    int base = win * 256;
    const float* qp = qkv + (base + qi) * 540 + head * HD;
    float q[HD];
#pragma unroll
    for (int d = 0; d < HD; d++) q[d] = qp[d] * 0.18257418583505536f;  // 30^-0.5
    float o[HD];
#pragma unroll
    for (int d = 0; d < HD; d++) o[d] = 0.f;
    float mx = -1e30f, l = 0.f;
    const float* rb = rpb + head * 65536 + qi * 256;
    const float* mk = mask + win * 65536 + qi * 256;
    for (int kt = 0; kt < 8; kt++) {
        __syncthreads();
        for (int idx = threadIdx.x; idx < 32 * HD; idx += 256) {
            int j = idx / HD, d = idx % HD;
            int tok = base + kt * 32 + j;
            ks[j][d] = qkv[tok * 540 + 180 + head * HD + d];
            vs[j][d] = qkv[tok * 540 + 360 + head * HD + d];
        }
        __syncthreads();
        float s[32];
        float cm = -1e30f;
#pragma unroll
        for (int j = 0; j < 32; j++) {
            float a = 0.f;
#pragma unroll
            for (int d2 = 0; d2 < 15; d2++) {
                float2 kv = *(const float2*)&ks[j][d2 * 2];
                a += q[d2 * 2] * kv.x + q[d2 * 2 + 1] * kv.y;
            }
            s[j] = a + rb[kt * 32 + j] + mk[kt * 32 + j];
            cm = fmaxf(cm, s[j]);
        }
        float nm = fmaxf(mx, cm);
        float corr = __expf(mx - nm);
        l *= corr;
#pragma unroll
        for (int d = 0; d < HD; d++) o[d] *= corr;
#pragma unroll
        for (int j = 0; j < 32; j++) {
            float p = __expf(s[j] - nm);
            l += p;
#pragma unroll
            for (int d2 = 0; d2 < 15; d2++) {
                float2 vv = *(const float2*)&vs[j][d2 * 2];
                o[d2 * 2] += p * vv.x;
                o[d2 * 2 + 1] += p * vv.y;
            }
        }
        mx = nm;
    }
    float inv = 1.0f / l;
    float* op = out + (base + qi) * CDIM + head * HD;
#pragma unroll
    for (int d = 0; d < HD; d++) op[d] = o[d] * inv;
}

// ---------------- residual combine + LN2 (warp per token) ----------------
__global__ void combine_ln2(const float* __restrict__ x, const float* __restrict__ proj,
                            const float* __restrict__ y2, const float* __restrict__ ca,
                            const float* __restrict__ g2, const float* __restrict__ b2,
                            float* __restrict__ x1, float* __restrict__ xm) {
    int p = blockIdx.x * 8 + (threadIdx.x >> 5);
    int lane = threadIdx.x & 31;
    int r = p >> 8, cc = p & 255;
    int hs = (r + 248) & 255;
    int ws2 = (cc + 248) & 255;
    int widx = (((hs >> 4) << 4) + (ws2 >> 4)) * 256 + ((hs & 15) << 4) + (ws2 & 15);
    float v[6];
    float s = 0.f;
#pragma unroll
    for (int k = 0; k < 6; k++) {
        int c = k * 32 + lane;
        if (c < CDIM) {
            v[k] = x[p * CDIM + c] + proj[widx * CDIM + c] + 0.01f * y2[p * CDIM + c] * ca[c];
        } else v[k] = 0.f;
        s += v[k];
    }
    s = warp_sum(s);
    float mu = s * (1.0f / CDIM);
    float sq = 0.f;
#pragma unroll
    for (int k = 0; k < 6; k++) {
        int c = k * 32 + lane;
        if (c < CDIM) { float d = v[k] - mu; sq += d * d; }
    }
    sq = warp_sum(sq);
    float rstd = rsqrtf(sq * (1.0f / CDIM) + 1e-5f);
#pragma unroll
    for (int k = 0; k < 6; k++) {
        int c = k * 32 + lane;
        if (c < CDIM) {
            x1[p * CDIM + c] = v[k];
            xm[p * CDIM + c] = (v[k] - mu) * rstd * g2[c] + b2[c];
        }
    }
}

// ---------------- launcher ----------------
extern "C" void kernel_launch(void* const* d_in, const int* in_sizes, int n_in,
                              void* d_out, int out_size) {
    const float* x     = (const float*)d_in[0];
    const int*   rpi   = (const int*)d_in[3];
    const float* mask  = (const float*)d_in[4];
    const float* n1g   = (const float*)d_in[5];
    const float* n1b   = (const float*)d_in[6];
    const float* qkvw  = (const float*)d_in[7];
    const float* qkvb  = (const float*)d_in[8];
    const float* rpbt  = (const float*)d_in[9];
    const float* projw = (const float*)d_in[10];
    const float* projb = (const float*)d_in[11];
    const float* c1w   = (const float*)d_in[12];
    const float* c1b   = (const float*)d_in[13];
    const float* c2w   = (const float*)d_in[14];
    const float* c2b   = (const float*)d_in[15];
    const float* ca1w  = (const float*)d_in[16];
    const float* ca1b  = (const float*)d_in[17];
    const float* ca2w  = (const float*)d_in[18];
    const float* ca2b  = (const float*)d_in[19];
    const float* n2g   = (const float*)d_in[20];
    const float* n2b   = (const float*)d_in[21];
    const float* f1w   = (const float*)d_in[22];
    const float* f1b   = (const float*)d_in[23];
    const float* f2w   = (const float*)d_in[24];
    const float* f2b   = (const float*)d_in[25];
    float* out = (float*)d_out;

    float *xn, *xnT, *xw, *qkv, *attn, *proj, *y1T, *y2, *rpb, *casum, *ca, *x1, *xm, *mb;
    cudaGetSymbolAddress((void**)&xn, g_xn);
    cudaGetSymbolAddress((void**)&xnT, g_xnT);
    cudaGetSymbolAddress((void**)&xw, g_xw);
    cudaGetSymbolAddress((void**)&qkv, g_qkv);
    cudaGetSymbolAddress((void**)&attn, g_attn);
    cudaGetSymbolAddress((void**)&proj, g_proj);
    cudaGetSymbolAddress((void**)&y1T, g_y1T);
    cudaGetSymbolAddress((void**)&y2, g_y2);
    cudaGetSymbolAddress((void**)&rpb, g_rpb);
    cudaGetSymbolAddress((void**)&casum, g_casum);
    cudaGetSymbolAddress((void**)&ca, g_ca);
    cudaGetSymbolAddress((void**)&x1, g_x1);
    cudaGetSymbolAddress((void**)&xm, g_xm);
    cudaGetSymbolAddress((void**)&mb, g_mb);

    dim3 t16(16, 16);

    ln_kernel<<<NP / 8, 256>>>(x, n1g, n1b, xn);
    transpose_kernel<<<dim3(6, 2048), dim3(32, 8)>>>(xn, xnT);
    gather_kernel<<<NP, 192>>>(xn, xw);
    rpb_kernel<<<256, 256>>>(rpi, rpbt, rpb);

    // qkv projection on windowed tokens
    gemm_kernel<0><<<dim3(9, 1024), t16>>>(xw, qkvw, qkvb, nullptr, qkv, NP, 540, 180);
    attn_kernel<<<dim3(256, 6), 256>>>(qkv, rpb, mask, attn);
    gemm_kernel<0><<<dim3(3, 1024), t16>>>(attn, projw, projb, nullptr, proj, NP, 180, 180);

    // conv branch
    conv1_kernel<<<1024, t16>>>(xnT, c1w, c1b, y1T);
    conv2_kernel<<<dim3(1024, 3), t16>>>(y1T, c2w, c2b, y2);
    cudaMemsetAsync(casum, 0, CDIM * sizeof(float));
    pool_kernel<<<256, 192>>>(y2, casum);
    ca_kernel<<<1, 192>>>(casum, ca1w, ca1b, ca2w, ca2b, ca);

    // combine + LN2 + MLP
    combine_ln2<<<NP / 8, 256>>>(x, proj, y2, ca, n2g, n2b, x1, xm);
    gemm_kernel<1><<<dim3(12, 1024), t16>>>(xm, f1w, f1b, nullptr, mb, NP, HID, 180);
    gemm_kernel<2><<<dim3(3, 1024), t16>>>(mb, f2w, f2b, x1, out, NP, CDIM, HID);
}

// round 3
// speedup vs baseline: 1.2751x; 1.2751x over previous
#include <cuda_runtime.h>
#include <cuda_bf16.h>
#include <math.h>
#include <stdint.h>

#define NP 65536
#define CDIM 180
#define NHEADS 6
#define HD 30
#define HID 720
#define KP1 192
#define KP2 768

// ---------------- scratch (device globals; no allocations) ----------------
__device__ __align__(16) float g_xn[NP * CDIM];
__device__ __align__(16) float g_xnT[CDIM * NP];
__device__ __align__(16) float g_qkv[NP * 540];
__device__ __align__(16) float g_proj[NP * CDIM];
__device__ __align__(16) float g_y1T[60 * NP];
__device__ __align__(16) float g_y2[NP * CDIM];
__device__ __align__(16) float g_rpb[NHEADS * 65536];
__device__ float g_casum[CDIM];
__device__ float g_ca[CDIM];
__device__ __align__(16) float g_x1[NP * CDIM];
// bf16 split activations (zero-initialized; K-pad columns stay zero forever)
__device__ __align__(16) __nv_bfloat16 g_ahi[NP * KP1];
__device__ __align__(16) __nv_bfloat16 g_alo[NP * KP1];
__device__ __align__(16) __nv_bfloat16 g_mhi[NP * KP2];
__device__ __align__(16) __nv_bfloat16 g_mlo[NP * KP2];
// bf16 split transposed weights [N_pad][K_pad]
__device__ __align__(16) __nv_bfloat16 g_bqh[576 * KP1], g_bql[576 * KP1];
__device__ __align__(16) __nv_bfloat16 g_bph[192 * KP1], g_bpl[192 * KP1];
__device__ __align__(16) __nv_bfloat16 g_b1h[768 * KP1], g_b1l[768 * KP1];
__device__ __align__(16) __nv_bfloat16 g_b2h[192 * KP2], g_b2l[192 * KP2];

__device__ __forceinline__ float gelu_f(float x) {
    return 0.5f * x * (1.0f + erff(x * 0.70710678118654752f));
}
__device__ __forceinline__ float warp_sum(float v) {
    for (int o = 16; o > 0; o >>= 1) v += __shfl_xor_sync(0xffffffffu, v, o);
    return v;
}
__device__ __forceinline__ void store_hilo(__nv_bfloat16* h, __nv_bfloat16* l,
                                           size_t idx, float v) {
    __nv_bfloat16 hh = __float2bfloat16(v);
    h[idx] = hh;
    l[idx] = __float2bfloat16(v - __bfloat162float(hh));
}
__device__ __forceinline__ uint32_t smem_u32(const void* p) {
    uint32_t a;
    asm("{ .reg .u64 t; cvta.to.shared.u64 t, %1; cvt.u32.u64 %0, t; }" : "=r"(a) : "l"(p));
    return a;
}
__device__ __forceinline__ void ldsm_x4(uint32_t& r0, uint32_t& r1, uint32_t& r2, uint32_t& r3,
                                        uint32_t addr) {
    asm volatile("ldmatrix.sync.aligned.m8n8.x4.shared.b16 {%0,%1,%2,%3}, [%4];"
                 : "=r"(r0), "=r"(r1), "=r"(r2), "=r"(r3) : "r"(addr));
}
__device__ __forceinline__ void mma_bf16(float* c, const uint32_t* a, const uint32_t* b) {
    asm volatile(
        "mma.sync.aligned.m16n8k16.row.col.f32.bf16.bf16.f32 "
        "{%0,%1,%2,%3}, {%4,%5,%6,%7}, {%8,%9}, {%0,%1,%2,%3};"
        : "+f"(c[0]), "+f"(c[1]), "+f"(c[2]), "+f"(c[3])
        : "r"(a[0]), "r"(a[1]), "r"(a[2]), "r"(a[3]), "r"(b[0]), "r"(b[1]));
}

// ---------------- weight prep: W[K,N] -> hi/lo [N_pad,K_pad] ----------------
__global__ void prepb_kernel(const float* __restrict__ W, int K, int N, int K_pad, int N_pad,
                             __nv_bfloat16* __restrict__ bh, __nv_bfloat16* __restrict__ bl) {
    int idx = blockIdx.x * 256 + threadIdx.x;
    if (idx >= N_pad * K_pad) return;
    int n = idx / K_pad, k = idx % K_pad;
    float v = (n < N && k < K) ? W[k * N + n] : 0.f;
    __nv_bfloat16 h = __float2bfloat16(v);
    bh[idx] = h;
    bl[idx] = __float2bfloat16(v - __bfloat162float(h));
}

// ---------------- HMMA bf16-split GEMM ----------------
// C[M, Nvalid] = A[M, Kpad] * B[Npad, Kpad]^T + bias ; A/B as hi/lo bf16.
// EPI: 0 = bias -> fp32 ; 1 = bias+gelu -> hi/lo bf16 ; 2 = bias+residual -> fp32
#define LDA 72   // padded bf16 per smem row (144 bytes)
#define SM_AHI 0
#define SM_ALO 18432
#define SM_BHI 36864
#define SM_BLO 46080
#define TC_SMEM_BYTES 55296

template <int EPI>
__global__ void __launch_bounds__(256) tc_gemm(
    const __nv_bfloat16* __restrict__ Ahi, const __nv_bfloat16* __restrict__ Alo,
    const __nv_bfloat16* __restrict__ Bhi, const __nv_bfloat16* __restrict__ Blo,
    const float* __restrict__ bias, const float* __restrict__ res,
    float* __restrict__ Cf, __nv_bfloat16* __restrict__ Chi, __nv_bfloat16* __restrict__ Clo,
    int Nvalid, int ldc, int Kpad, int nchunks) {
    extern __shared__ __align__(16) char sm[];
    const uint32_t smb = smem_u32(sm);
    const int tid = threadIdx.x;
    const int wid = tid >> 5, lane = tid & 31;
    const int wm = wid >> 1, wn = wid & 1;
    const int m0 = blockIdx.y * 128;
    const int n0 = blockIdx.x * 64;

    float acc[2][4][4] = {};

    // ldmatrix per-lane address pieces
    const int a_row = lane & 15;          // row within 16
    const int a_koff = (lane >> 4) << 3;  // 0 or 8
    const int b_grp = lane >> 3;
    const int b_n = ((b_grp & 1) << 3) + (lane & 7);
    const int b_koff = (b_grp >> 1) << 3;

    for (int ch = 0; ch < nchunks; ch++) {
        const int k0 = ch * 64;
        // global -> smem : A 128x64 hi/lo
#pragma unroll
        for (int it = 0; it < 4; it++) {
            int c = tid + it * 256;            // 0..1023
            int r = c >> 3, ko = (c & 7) << 3; // ko in bf16 elems
            size_t ga = (size_t)(m0 + r) * Kpad + k0 + ko;
            uint32_t so = r * (LDA * 2) + ko * 2;
            *(uint4*)(sm + SM_AHI + so) = *(const uint4*)(Ahi + ga);
            *(uint4*)(sm + SM_ALO + so) = *(const uint4*)(Alo + ga);
        }
        // B 64x64 hi/lo
#pragma unroll
        for (int it = 0; it < 2; it++) {
            int c = tid + it * 256;
            int r = c >> 3, ko = (c & 7) << 3;
            size_t gb = (size_t)(n0 + r) * Kpad + k0 + ko;
            uint32_t so = r * (LDA * 2) + ko * 2;
            *(uint4*)(sm + SM_BHI + so) = *(const uint4*)(Bhi + gb);
            *(uint4*)(sm + SM_BLO + so) = *(const uint4*)(Blo + gb);
        }
        __syncthreads();

#pragma unroll
        for (int pass = 0; pass < 3; pass++) {
            const uint32_t aBase = smb + (pass == 2 ? SM_ALO : SM_AHI);
            const uint32_t bBase = smb + (pass == 1 ? SM_BLO : SM_BHI);
#pragma unroll
            for (int ks = 0; ks < 4; ks++) {
                uint32_t a[2][4], b[2][4];
#pragma unroll
                for (int mt = 0; mt < 2; mt++) {
                    uint32_t ad = aBase +
                        (uint32_t)((wm * 32 + mt * 16 + a_row) * (LDA * 2) +
                                   (ks * 16 + a_koff) * 2);
                    ldsm_x4(a[mt][0], a[mt][1], a[mt][2], a[mt][3], ad);
                }
#pragma unroll
                for (int np = 0; np < 2; np++) {
                    uint32_t bd = bBase +
                        (uint32_t)((wn * 32 + np * 16 + b_n) * (LDA * 2) +
                                   (ks * 16 + b_koff) * 2);
                    ldsm_x4(b[np][0], b[np][1], b[np][2], b[np][3], bd);
                }
                // b[np] regs: {b0 of nt=2np, b0 of nt=2np+1, b1 of nt=2np, b1 of nt=2np+1}
#pragma unroll
                for (int mt = 0; mt < 2; mt++) {
#pragma unroll
                    for (int np = 0; np < 2; np++) {
                        uint32_t bfr0[2] = { b[np][0], b[np][2] };
                        uint32_t bfr1[2] = { b[np][1], b[np][3] };
                        mma_bf16(acc[mt][2 * np + 0], a[mt], bfr0);
                        mma_bf16(acc[mt][2 * np + 1], a[mt], bfr1);
                    }
                }
            }
        }
        __syncthreads();
    }

    // epilogue: c fragment (row = lane/4 + {0,8}, col = 2*(lane%4) + {0,1})
    const int r_in = lane >> 2;
    const int c_in = (lane & 3) << 1;
#pragma unroll
    for (int mt = 0; mt < 2; mt++) {
        int mrow = m0 + wm * 32 + mt * 16 + r_in;
#pragma unroll
        for (int nt = 0; nt < 4; nt++) {
            int col = n0 + wn * 32 + nt * 8 + c_in;
#pragma unroll
            for (int e = 0; e < 4; e++) {
                int rr = mrow + ((e >> 1) << 3);
                int cc = col + (e & 1);
                if (cc < Nvalid) {
                    float v = acc[mt][nt][e] + bias[cc];
                    if (EPI == 0) {
                        Cf[(size_t)rr * ldc + cc] = v;
                    } else if (EPI == 1) {
                        store_hilo(Chi, Clo, (size_t)rr * ldc + cc, gelu_f(v));
                    } else {
                        Cf[(size_t)rr * ldc + cc] = v + res[(size_t)rr * Nvalid + cc];
                    }
                }
            }
        }
    }
}

// ---------------- LayerNorm (one warp per token) ----------------
__global__ void ln_kernel(const float* __restrict__ x, const float* __restrict__ g,
                          const float* __restrict__ b, float* __restrict__ out) {
    int p = blockIdx.x * 8 + (threadIdx.x >> 5);
    int lane = threadIdx.x & 31;
    const float* xr = x + (size_t)p * CDIM;
    float v[6];
    float s = 0.f;
#pragma unroll
    for (int k = 0; k < 6; k++) {
        int c = k * 32 + lane;
        v[k] = (c < CDIM) ? xr[c] : 0.f;
        s += v[k];
    }
    s = warp_sum(s);
    float mu = s * (1.0f / CDIM);
    float sq = 0.f;
#pragma unroll
    for (int k = 0; k < 6; k++) {
        int c = k * 32 + lane;
        if (c < CDIM) { float d = v[k] - mu; sq += d * d; }
    }
    sq = warp_sum(sq);
    float rstd = rsqrtf(sq * (1.0f / CDIM) + 1e-5f);
    float* orow = out + (size_t)p * CDIM;
#pragma unroll
    for (int k = 0; k < 6; k++) {
        int c = k * 32 + lane;
        if (c < CDIM) orow[c] = (v[k] - mu) * rstd * g[c] + b[c];
    }
}

// ---------------- transpose [NP][C] -> [C][NP] ----------------
__global__ void transpose_kernel(const float* __restrict__ in, float* __restrict__ out) {
    __shared__ float tile[32][33];
    int c0 = blockIdx.x * 32;
    int p0 = blockIdx.y * 32;
    int tx = threadIdx.x, ty = threadIdx.y;
    for (int i = ty; i < 32; i += 8) {
        int c = c0 + tx;
        tile[i][tx] = (c < CDIM) ? in[(size_t)(p0 + i) * CDIM + c] : 0.f;
    }
    __syncthreads();
    for (int i = ty; i < 32; i += 8) {
        int c = c0 + i;
        if (c < CDIM) out[(size_t)c * NP + p0 + tx] = tile[tx][i];
    }
}

// ---------------- roll + window gather -> bf16 hi/lo A ----------------
__global__ void gather_kernel(const float* __restrict__ xn,
                              __nv_bfloat16* __restrict__ ah, __nv_bfloat16* __restrict__ al) {
    int widx = blockIdx.x;
    int c = threadIdx.x;
    if (c >= CDIM) return;
    int win = widx >> 8, tok = widx & 255;
    int hs = ((win >> 4) << 4) + (tok >> 4);
    int ws2 = ((win & 15) << 4) + (tok & 15);
    int hr = (hs + 8) & 255;
    int wr = (ws2 + 8) & 255;
    float v = xn[(size_t)(hr * 256 + wr) * CDIM + c];
    store_hilo(ah, al, (size_t)widx * KP1 + c, v);
}

// ---------------- relative position bias ----------------
__global__ void rpb_kernel(const int* __restrict__ rpi, const float* __restrict__ table,
                           float* __restrict__ rpb) {
    int idx = blockIdx.x * 256 + threadIdx.x;
    int r = rpi[idx];
#pragma unroll
    for (int h = 0; h < NHEADS; h++) rpb[h * 65536 + idx] = table[r * NHEADS + h];
}

// ---------------- conv1: [180][NP] -> gelu -> [60][NP] ----------------
__global__ void conv1_kernel(const float* __restrict__ in, const float* __restrict__ w,
                             const float* __restrict__ bias, float* __restrict__ out) {
    __shared__ float As[16][64];
    __shared__ float Bs[16][64];
    int tile = blockIdx.x;
    int row = tile >> 2, seg = tile & 3;
    int cb = seg * 64;
    int pbase = row * 256 + cb;
    int tid = threadIdx.y * 16 + threadIdx.x;
    int lkk = tid >> 4;
    int lp4 = (tid & 15) * 4;
    float acc[4][4] = {};
    for (int t = 0; t < 9; t++) {
        int dy = t / 3 - 1, dx = t % 3 - 1;
        int r2 = row + dy;
        bool rok = ((unsigned)r2 < 256u);
        for (int icb = 0; icb < 180; icb += 16) {
            int ic = icb + lkk;
#pragma unroll
            for (int q = 0; q < 4; q++) {
                int px = lp4 + q;
                int col = cb + px + dx;
                float v = 0.f;
                if (rok && (unsigned)col < 256u && ic < 180)
                    v = in[(size_t)ic * NP + r2 * 256 + col];
                As[lkk][px] = v;
            }
#pragma unroll
            for (int q = 0; q < 4; q++) {
                int oc = lp4 + q;
                float v = 0.f;
                if (oc < 60 && ic < 180) v = w[(oc * 180 + ic) * 9 + t];
                Bs[lkk][oc] = v;
            }
            __syncthreads();
#pragma unroll
            for (int kk = 0; kk < 16; kk++) {
                float4 a4 = *(const float4*)&As[kk][threadIdx.y * 4];
                float4 b4 = *(const float4*)&Bs[kk][threadIdx.x * 4];
                acc[0][0] += a4.x * b4.x; acc[0][1] += a4.x * b4.y; acc[0][2] += a4.x * b4.z; acc[0][3] += a4.x * b4.w;
                acc[1][0] += a4.y * b4.x; acc[1][1] += a4.y * b4.y; acc[1][2] += a4.y * b4.z; acc[1][3] += a4.y * b4.w;
                acc[2][0] += a4.z * b4.x; acc[2][1] += a4.z * b4.y; acc[2][2] += a4.z * b4.z; acc[2][3] += a4.z * b4.w;
                acc[3][0] += a4.w * b4.x; acc[3][1] += a4.w * b4.y; acc[3][2] += a4.w * b4.z; acc[3][3] += a4.w * b4.w;
            }
            __syncthreads();
        }
    }
    int py = threadIdx.y * 4;
#pragma unroll
    for (int j = 0; j < 4; j++) {
        int oc = threadIdx.x * 4 + j;
        if (oc < 60) {
            float b0 = bias[oc];
            float4 v;
            v.x = gelu_f(acc[0][j] + b0);
            v.y = gelu_f(acc[1][j] + b0);
            v.z = gelu_f(acc[2][j] + b0);
            v.w = gelu_f(acc[3][j] + b0);
            *(float4*)&out[(size_t)oc * NP + pbase + py] = v;
        }
    }
}

// ---------------- conv2: [60][NP] -> [NP][180] ----------------
__global__ void conv2_kernel(const float* __restrict__ in, const float* __restrict__ w,
                             const float* __restrict__ bias, float* __restrict__ out) {
    __shared__ float As[16][64];
    __shared__ float Bs[16][64];
    int tile = blockIdx.x;
    int n0 = blockIdx.y * 64;
    int row = tile >> 2, seg = tile & 3;
    int cb = seg * 64;
    int pbase = row * 256 + cb;
    int tid = threadIdx.y * 16 + threadIdx.x;
    int lkk = tid >> 4;
    int lp4 = (tid & 15) * 4;
    float acc[4][4] = {};
    for (int t = 0; t < 9; t++) {
        int dy = t / 3 - 1, dx = t % 3 - 1;
        int r2 = row + dy;
        bool rok = ((unsigned)r2 < 256u);
        for (int icb = 0; icb < 60; icb += 16) {
            int ic = icb + lkk;
#pragma unroll
            for (int q = 0; q < 4; q++) {
                int px = lp4 + q;
                int col = cb + px + dx;
                float v = 0.f;
                if (rok && (unsigned)col < 256u && ic < 60)
                    v = in[(size_t)ic * NP + r2 * 256 + col];
                As[lkk][px] = v;
            }
#pragma unroll
            for (int q = 0; q < 4; q++) {
                int oc = n0 + lp4 + q;
                float v = 0.f;
                if (oc < 180 && ic < 60) v = w[(oc * 60 + ic) * 9 + t];
                Bs[lkk][lp4 + q] = v;
            }
            __syncthreads();
#pragma unroll
            for (int kk = 0; kk < 16; kk++) {
                float4 a4 = *(const float4*)&As[kk][threadIdx.y * 4];
                float4 b4 = *(const float4*)&Bs[kk][threadIdx.x * 4];
                acc[0][0] += a4.x * b4.x; acc[0][1] += a4.x * b4.y; acc[0][2] += a4.x * b4.z; acc[0][3] += a4.x * b4.w;
                acc[1][0] += a4.y * b4.x; acc[1][1] += a4.y * b4.y; acc[1][2] += a4.y * b4.z; acc[1][3] += a4.y * b4.w;
                acc[2][0] += a4.z * b4.x; acc[2][1] += a4.z * b4.y; acc[2][2] += a4.z * b4.z; acc[2][3] += a4.z * b4.w;
                acc[3][0] += a4.w * b4.x; acc[3][1] += a4.w * b4.y; acc[3][2] += a4.w * b4.z; acc[3][3] += a4.w * b4.w;
            }
            __syncthreads();
        }
    }
    int oc0 = n0 + threadIdx.x * 4;
    if (oc0 < 180) {
        float4 bb = *(const float4*)&bias[oc0];
#pragma unroll
        for (int i = 0; i < 4; i++) {
            int pix = pbase + threadIdx.y * 4 + i;
            float4 v;
            v.x = acc[i][0] + bb.x; v.y = acc[i][1] + bb.y;
            v.z = acc[i][2] + bb.z; v.w = acc[i][3] + bb.w;
            *(float4*)&out[(size_t)pix * CDIM + oc0] = v;
        }
    }
}

// ---------------- channel-attention pooling ----------------
__global__ void pool_kernel(const float* __restrict__ y2, float* __restrict__ casum) {
    int c = threadIdx.x;
    if (c >= CDIM) return;
    int p0 = blockIdx.x * 256;
    float s = 0.f;
    for (int i = 0; i < 256; i++) s += y2[(size_t)(p0 + i) * CDIM + c];
    atomicAdd(&casum[c], s);
}

__global__ void ca_kernel(const float* __restrict__ casum,
                          const float* __restrict__ w1, const float* __restrict__ b1,
                          const float* __restrict__ w2, const float* __restrict__ b2,
                          float* __restrict__ ca) {
    __shared__ float mean[CDIM];
    __shared__ float sq[6];
    int t = threadIdx.x;
    if (t < CDIM) mean[t] = casum[t] * (1.0f / NP);
    __syncthreads();
    if (t < 6) {
        float a = b1[t];
        for (int c = 0; c < CDIM; c++) a += mean[c] * w1[t * CDIM + c];
        sq[t] = fmaxf(a, 0.f);
    }
    __syncthreads();
    if (t < CDIM) {
        float a = b2[t];
#pragma unroll
        for (int s = 0; s < 6; s++) a += sq[s] * w2[t * 6 + s];
        ca[t] = 1.0f / (1.0f + __expf(-a));
    }
}

// ---------------- flash attention per (window, head), writes bf16 hi/lo ----------------
__global__ void __launch_bounds__(256) attn_kernel(const float* __restrict__ qkv,
                                                   const float* __restrict__ rpb,
                                                   const float* __restrict__ mask,
                                                   __nv_bfloat16* __restrict__ oh,
                                                   __nv_bfloat16* __restrict__ ol) {
    int win = blockIdx.x;
    int head = blockIdx.y;
    __shared__ float ks[32][30];
    __shared__ float vs[32][30];
    int qi = threadIdx.x;
    int base = win * 256;
    const float* qp = qkv + (size_t)(base + qi) * 540 + head * HD;
    float q[HD];
#pragma unroll
    for (int d = 0; d < HD; d++) q[d] = qp[d] * 0.18257418583505536f;
    float o[HD];
#pragma unroll
    for (int d = 0; d < HD; d++) o[d] = 0.f;
    float mx = -1e30f, l = 0.f;
    const float* rb = rpb + (size_t)head * 65536 + qi * 256;
    const float* mk = mask + (size_t)win * 65536 + qi * 256;
    for (int kt = 0; kt < 8; kt++) {
        __syncthreads();
        for (int idx = threadIdx.x; idx < 32 * HD; idx += 256) {
            int j = idx / HD, d = idx % HD;
            size_t tok = (size_t)(base + kt * 32 + j) * 540;
            ks[j][d] = qkv[tok + 180 + head * HD + d];
            vs[j][d] = qkv[tok + 360 + head * HD + d];
        }
        __syncthreads();
        float s[32];
        float cm = -1e30f;
#pragma unroll
        for (int j = 0; j < 32; j++) {
            float a = 0.f;
#pragma unroll
            for (int d2 = 0; d2 < 15; d2++) {
                float2 kv = *(const float2*)&ks[j][d2 * 2];
                a += q[d2 * 2] * kv.x + q[d2 * 2 + 1] * kv.y;
            }
            s[j] = a + rb[kt * 32 + j] + mk[kt * 32 + j];
            cm = fmaxf(cm, s[j]);
        }
        float nm = fmaxf(mx, cm);
        float corr = __expf(mx - nm);
        l *= corr;
#pragma unroll
        for (int d = 0; d < HD; d++) o[d] *= corr;
#pragma unroll
        for (int j = 0; j < 32; j++) {
            float p = __expf(s[j] - nm);
            l += p;
#pragma unroll
            for (int d2 = 0; d2 < 15; d2++) {
                float2 vv = *(const float2*)&vs[j][d2 * 2];
                o[d2 * 2] += p * vv.x;
                o[d2 * 2 + 1] += p * vv.y;
            }
        }
        mx = nm;
    }
    float inv = 1.0f / l;
    size_t ob = (size_t)(base + qi) * KP1 + head * HD;
#pragma unroll
    for (int d = 0; d < HD; d++) store_hilo(oh, ol, ob + d, o[d] * inv);
}

// ---------------- residual combine + LN2: x1 fp32 + xm hi/lo ----------------
__global__ void combine_ln2(const float* __restrict__ x, const float* __restrict__ proj,
                            const float* __restrict__ y2, const float* __restrict__ ca,
                            const float* __restrict__ g2, const float* __restrict__ b2,
                            float* __restrict__ x1,
                            __nv_bfloat16* __restrict__ mh, __nv_bfloat16* __restrict__ ml) {
    int p = blockIdx.x * 8 + (threadIdx.x >> 5);
    int lane = threadIdx.x & 31;
    int r = p >> 8, cc = p & 255;
    int hs = (r + 248) & 255;
    int ws2 = (cc + 248) & 255;
    int widx = (((hs >> 4) << 4) + (ws2 >> 4)) * 256 + ((hs & 15) << 4) + (ws2 & 15);
    float v[6];
    float s = 0.f;
#pragma unroll
    for (int k = 0; k < 6; k++) {
        int c = k * 32 + lane;
        if (c < CDIM) {
            v[k] = x[(size_t)p * CDIM + c] + proj[(size_t)widx * CDIM + c]
                 + 0.01f * y2[(size_t)p * CDIM + c] * ca[c];
        } else v[k] = 0.f;
        s += v[k];
    }
    s = warp_sum(s);
    float mu = s * (1.0f / CDIM);
    float sq = 0.f;
#pragma unroll
    for (int k = 0; k < 6; k++) {
        int c = k * 32 + lane;
        if (c < CDIM) { float d = v[k] - mu; sq += d * d; }
    }
    sq = warp_sum(sq);
    float rstd = rsqrtf(sq * (1.0f / CDIM) + 1e-5f);
#pragma unroll
    for (int k = 0; k < 6; k++) {
        int c = k * 32 + lane;
        if (c < CDIM) {
            x1[(size_t)p * CDIM + c] = v[k];
            store_hilo(mh, ml, (size_t)p * KP1 + c, (v[k] - mu) * rstd * g2[c] + b2[c]);
        }
    }
}

// ---------------- launcher ----------------
extern "C" void kernel_launch(void* const* d_in, const int* in_sizes, int n_in,
                              void* d_out, int out_size) {
    const float* x     = (const float*)d_in[0];
    const int*   rpi   = (const int*)d_in[3];
    const float* mask  = (const float*)d_in[4];
    const float* n1g   = (const float*)d_in[5];
    const float* n1b   = (const float*)d_in[6];
    const float* qkvw  = (const float*)d_in[7];
    const float* qkvb  = (const float*)d_in[8];
    const float* rpbt  = (const float*)d_in[9];
    const float* projw = (const float*)d_in[10];
    const float* projb = (const float*)d_in[11];
    const float* c1w   = (const float*)d_in[12];
    const float* c1b   = (const float*)d_in[13];
    const float* c2w   = (const float*)d_in[14];
    const float* c2b   = (const float*)d_in[15];
    const float* ca1w  = (const float*)d_in[16];
    const float* ca1b  = (const float*)d_in[17];
    const float* ca2w  = (const float*)d_in[18];
    const float* ca2b  = (const float*)d_in[19];
    const float* n2g   = (const float*)d_in[20];
    const float* n2b   = (const float*)d_in[21];
    const float* f1w   = (const float*)d_in[22];
    const float* f1b   = (const float*)d_in[23];
    const float* f2w   = (const float*)d_in[24];
    const float* f2b   = (const float*)d_in[25];
    float* out = (float*)d_out;

    float *xn, *xnT, *qkv, *proj, *y1T, *y2, *rpb, *casum, *ca, *x1;
    __nv_bfloat16 *ahi, *alo, *mhi, *mlo;
    __nv_bfloat16 *bqh, *bql, *bph, *bpl, *b1h, *b1l, *b2h, *b2l;
    cudaGetSymbolAddress((void**)&xn, g_xn);
    cudaGetSymbolAddress((void**)&xnT, g_xnT);
    cudaGetSymbolAddress((void**)&qkv, g_qkv);
    cudaGetSymbolAddress((void**)&proj, g_proj);
    cudaGetSymbolAddress((void**)&y1T, g_y1T);
    cudaGetSymbolAddress((void**)&y2, g_y2);
    cudaGetSymbolAddress((void**)&rpb, g_rpb);
    cudaGetSymbolAddress((void**)&casum, g_casum);
    cudaGetSymbolAddress((void**)&ca, g_ca);
    cudaGetSymbolAddress((void**)&x1, g_x1);
    cudaGetSymbolAddress((void**)&ahi, g_ahi);
    cudaGetSymbolAddress((void**)&alo, g_alo);
    cudaGetSymbolAddress((void**)&mhi, g_mhi);
    cudaGetSymbolAddress((void**)&mlo, g_mlo);
    cudaGetSymbolAddress((void**)&bqh, g_bqh);
    cudaGetSymbolAddress((void**)&bql, g_bql);
    cudaGetSymbolAddress((void**)&bph, g_bph);
    cudaGetSymbolAddress((void**)&bpl, g_bpl);
    cudaGetSymbolAddress((void**)&b1h, g_b1h);
    cudaGetSymbolAddress((void**)&b1l, g_b1l);
    cudaGetSymbolAddress((void**)&b2h, g_b2h);
    cudaGetSymbolAddress((void**)&b2l, g_b2l);

    cudaFuncSetAttribute(tc_gemm<0>, cudaFuncAttributeMaxDynamicSharedMemorySize, TC_SMEM_BYTES);
    cudaFuncSetAttribute(tc_gemm<1>, cudaFuncAttributeMaxDynamicSharedMemorySize, TC_SMEM_BYTES);
    cudaFuncSetAttribute(tc_gemm<2>, cudaFuncAttributeMaxDynamicSharedMemorySize, TC_SMEM_BYTES);

    dim3 t16(16, 16);

    // weight prep (tiny)
    prepb_kernel<<<432, 256>>>(qkvw, 180, 540, KP1, 576, bqh, bql);
    prepb_kernel<<<144, 256>>>(projw, 180, 180, KP1, 192, bph, bpl);
    prepb_kernel<<<576, 256>>>(f1w, 180, 720, KP1, 768, b1h, b1l);
    prepb_kernel<<<576, 256>>>(f2w, 720, 180, KP2, 192, b2h, b2l);

    ln_kernel<<<NP / 8, 256>>>(x, n1g, n1b, xn);
    transpose_kernel<<<dim3(6, 2048), dim3(32, 8)>>>(xn, xnT);
    gather_kernel<<<NP, 192>>>(xn, ahi, alo);
    rpb_kernel<<<256, 256>>>(rpi, rpbt, rpb);

    // qkv projection (tensor core)
    tc_gemm<0><<<dim3(9, 512), 256, TC_SMEM_BYTES>>>(
        ahi, alo, bqh, bql, qkvb, nullptr, qkv, nullptr, nullptr, 540, 540, KP1, 3);
    attn_kernel<<<dim3(256, 6), 256>>>(qkv, rpb, mask, ahi, alo);
    tc_gemm<0><<<dim3(3, 512), 256, TC_SMEM_BYTES>>>(
        ahi, alo, bph, bpl, projb, nullptr, proj, nullptr, nullptr, 180, 180, KP1, 3);

    // conv branch
    conv1_kernel<<<1024, t16>>>(xnT, c1w, c1b, y1T);
    conv2_kernel<<<dim3(1024, 3), t16>>>(y1T, c2w, c2b, y2);
    cudaMemsetAsync(casum, 0, CDIM * sizeof(float));
    pool_kernel<<<256, 192>>>(y2, casum);
    ca_kernel<<<1, 192>>>(casum, ca1w, ca1b, ca2w, ca2b, ca);

    // combine + LN2 + MLP (tensor core)
    combine_ln2<<<NP / 8, 256>>>(x, proj, y2, ca, n2g, n2b, x1, ahi, alo);
    tc_gemm<1><<<dim3(12, 512), 256, TC_SMEM_BYTES>>>(
        ahi, alo, b1h, b1l, f1b, nullptr, nullptr, mhi, mlo, 720, KP2, KP1, 3);
    tc_gemm<2><<<dim3(3, 512), 256, TC_SMEM_BYTES>>>(
        mhi, mlo, b2h, b2l, f2b, x1, out, nullptr, nullptr, 180, 180, KP2, 12);
}

// round 4
// speedup vs baseline: 1.6075x; 1.2607x over previous
#include <cuda_runtime.h>
#include <cuda_bf16.h>
#include <math.h>
#include <stdint.h>

#define NP 65536
#define CDIM 180
#define NHEADS 6
#define HD 30
#define HID 720
#define KP1 192
#define KP2 768
#define PW 258   // padded image width/height

// ---------------- scratch (device globals; no allocations) ----------------
__device__ __align__(16) float g_xn[NP * CDIM];
__device__ __align__(16) float g_qkv[NP * 540];
__device__ __align__(16) float g_proj[NP * CDIM];
__device__ __align__(16) float g_y2[NP * CDIM];
__device__ __align__(16) float g_rpb[NHEADS * 65536];
__device__ float g_casum[CDIM];
__device__ float g_ca[CDIM];
__device__ __align__(16) float g_x1[NP * CDIM];
// padded bf16 image for conv branch (halo stays zero forever)
__device__ __align__(16) __nv_bfloat16 g_xnp[PW * PW * KP1];
__device__ __align__(16) __nv_bfloat16 g_y1p[PW * PW * 64];
// bf16 split activations (zero-initialized; K-pad columns stay zero forever)
__device__ __align__(16) __nv_bfloat16 g_ahi[NP * KP1];
__device__ __align__(16) __nv_bfloat16 g_alo[NP * KP1];
__device__ __align__(16) __nv_bfloat16 g_mhi[NP * KP2];
__device__ __align__(16) __nv_bfloat16 g_mlo[NP * KP2];
// bf16 split transposed weights [N_pad][K_pad]
__device__ __align__(16) __nv_bfloat16 g_bqh[576 * KP1], g_bql[576 * KP1];
__device__ __align__(16) __nv_bfloat16 g_bph[192 * KP1], g_bpl[192 * KP1];
__device__ __align__(16) __nv_bfloat16 g_b1h[768 * KP1], g_b1l[768 * KP1];
__device__ __align__(16) __nv_bfloat16 g_b2h[192 * KP2], g_b2l[192 * KP2];
// conv weights: [tap][ocpad][kpad]
__device__ __align__(16) __nv_bfloat16 g_wc1h[9 * 64 * KP1], g_wc1l[9 * 64 * KP1];
__device__ __align__(16) __nv_bfloat16 g_wc2h[9 * 192 * 64], g_wc2l[9 * 192 * 64];

__device__ __forceinline__ float gelu_f(float x) {
    return 0.5f * x * (1.0f + erff(x * 0.70710678118654752f));
}
__device__ __forceinline__ float warp_sum(float v) {
    for (int o = 16; o > 0; o >>= 1) v += __shfl_xor_sync(0xffffffffu, v, o);
    return v;
}
__device__ __forceinline__ void store_hilo(__nv_bfloat16* h, __nv_bfloat16* l,
                                           size_t idx, float v) {
    __nv_bfloat16 hh = __float2bfloat16(v);
    h[idx] = hh;
    l[idx] = __float2bfloat16(v - __bfloat162float(hh));
}
__device__ __forceinline__ uint32_t smem_u32(const void* p) {
    uint32_t a;
    asm("{ .reg .u64 t; cvta.to.shared.u64 t, %1; cvt.u32.u64 %0, t; }" : "=r"(a) : "l"(p));
    return a;
}
__device__ __forceinline__ void ldsm_x4(uint32_t& r0, uint32_t& r1, uint32_t& r2, uint32_t& r3,
                                        uint32_t addr) {
    asm volatile("ldmatrix.sync.aligned.m8n8.x4.shared.b16 {%0,%1,%2,%3}, [%4];"
                 : "=r"(r0), "=r"(r1), "=r"(r2), "=r"(r3) : "r"(addr));
}
__device__ __forceinline__ void mma_bf16(float* c, const uint32_t* a, const uint32_t* b) {
    asm volatile(
        "mma.sync.aligned.m16n8k16.row.col.f32.bf16.bf16.f32 "
        "{%0,%1,%2,%3}, {%4,%5,%6,%7}, {%8,%9}, {%0,%1,%2,%3};"
        : "+f"(c[0]), "+f"(c[1]), "+f"(c[2]), "+f"(c[3])
        : "r"(a[0]), "r"(a[1]), "r"(a[2]), "r"(a[3]), "r"(b[0]), "r"(b[1]));
}

// ---------------- weight prep: W[K,N] -> hi/lo [N_pad,K_pad] ----------------
__global__ void prepb_kernel(const float* __restrict__ W, int K, int N, int K_pad, int N_pad,
                             __nv_bfloat16* __restrict__ bh, __nv_bfloat16* __restrict__ bl) {
    int idx = blockIdx.x * 256 + threadIdx.x;
    if (idx >= N_pad * K_pad) return;
    int n = idx / K_pad, k = idx % K_pad;
    float v = (n < N && k < K) ? W[k * N + n] : 0.f;
    __nv_bfloat16 h = __float2bfloat16(v);
    bh[idx] = h;
    bl[idx] = __float2bfloat16(v - __bfloat162float(h));
}

// conv1 weights [60 oc][180 ic][3][3] -> [tap][64][192] hi/lo
__global__ void prepc1_kernel(const float* __restrict__ W,
                              __nv_bfloat16* __restrict__ bh, __nv_bfloat16* __restrict__ bl) {
    int idx = blockIdx.x * 256 + threadIdx.x;
    if (idx >= 9 * 64 * KP1) return;
    int k = idx % KP1;
    int rest = idx / KP1;
    int oc = rest % 64, tap = rest / 64;
    float v = (oc < 60 && k < 180) ? W[(oc * 180 + k) * 9 + tap] : 0.f;
    __nv_bfloat16 h = __float2bfloat16(v);
    bh[idx] = h;
    bl[idx] = __float2bfloat16(v - __bfloat162float(h));
}

// conv2 weights [180 oc][60 ic][3][3] -> [tap][192][64] hi/lo
__global__ void prepc2_kernel(const float* __restrict__ W,
                              __nv_bfloat16* __restrict__ bh, __nv_bfloat16* __restrict__ bl) {
    int idx = blockIdx.x * 256 + threadIdx.x;
    if (idx >= 9 * 192 * 64) return;
    int k = idx % 64;
    int rest = idx / 64;
    int oc = rest % 192, tap = rest / 192;
    float v = (oc < 180 && k < 60) ? W[(oc * 60 + k) * 9 + tap] : 0.f;
    __nv_bfloat16 h = __float2bfloat16(v);
    bh[idx] = h;
    bl[idx] = __float2bfloat16(v - __bfloat162float(h));
}

// ---------------- persistent-A HMMA GEMM (Kpad = 192) ----------------
// C[M, Nvalid] = A[M,192] * B[Npad,192]^T + bias ; 3-pass hi/lo split.
// EPI: 0 = bias -> fp32 ; 1 = bias+gelu -> hi/lo bf16
#define LDA2 200
#define G2_SMEM (128 * LDA2 * 2 * 2 + 64 * LDA2 * 2 * 2)  // 128000 bytes

template <int EPI>
__global__ void __launch_bounds__(256) tc_gemm2(
    const __nv_bfloat16* __restrict__ Ahi, const __nv_bfloat16* __restrict__ Alo,
    const __nv_bfloat16* __restrict__ Bhi, const __nv_bfloat16* __restrict__ Blo,
    const float* __restrict__ bias,
    float* __restrict__ Cf, __nv_bfloat16* __restrict__ Chi, __nv_bfloat16* __restrict__ Clo,
    int Nvalid, int ldc, int ntiles) {
    extern __shared__ __align__(16) char sm2[];
    __nv_bfloat16* sAh = (__nv_bfloat16*)sm2;
    __nv_bfloat16* sAl = sAh + 128 * LDA2;
    __nv_bfloat16* sBh = sAl + 128 * LDA2;
    __nv_bfloat16* sBl = sBh + 64 * LDA2;
    const uint32_t sAhu = smem_u32(sAh), sAlu = smem_u32(sAl);
    const uint32_t sBhu = smem_u32(sBh), sBlu = smem_u32(sBl);
    const int tid = threadIdx.x, wid = tid >> 5, lane = tid & 31;
    const int wm = wid >> 1, wn = wid & 1;
    const int m0 = blockIdx.x * 128;
    const int a_row = lane & 15, a_koff = (lane >> 4) << 3;
    const int b_grp = lane >> 3, b_n = ((b_grp & 1) << 3) + (lane & 7), b_koff = (b_grp >> 1) << 3;
    const int r_in = lane >> 2, c_in = (lane & 3) << 1;

    // load A once (128 x 192 hi/lo)
#pragma unroll
    for (int it = 0; it < 12; it++) {
        int c = tid + it * 256;
        int rr = c / 24, ko = (c % 24) * 8;
        size_t ga = (size_t)(m0 + rr) * KP1 + ko;
        *(uint4*)(sAh + rr * LDA2 + ko) = *(const uint4*)(Ahi + ga);
        *(uint4*)(sAl + rr * LDA2 + ko) = *(const uint4*)(Alo + ga);
    }

    for (int nt = 0; nt < ntiles; nt++) {
        const int n0 = nt * 64;
        __syncthreads();
#pragma unroll
        for (int it = 0; it < 6; it++) {
            int c = tid + it * 256;
            int rr = c / 24, ko = (c % 24) * 8;
            size_t gb = (size_t)(n0 + rr) * KP1 + ko;
            *(uint4*)(sBh + rr * LDA2 + ko) = *(const uint4*)(Bhi + gb);
            *(uint4*)(sBl + rr * LDA2 + ko) = *(const uint4*)(Blo + gb);
        }
        __syncthreads();

        float acc[2][4][4] = {};
#pragma unroll
        for (int pass = 0; pass < 3; pass++) {
            const uint32_t aBase = (pass == 2) ? sAlu : sAhu;
            const uint32_t bBase = (pass == 1) ? sBlu : sBhu;
#pragma unroll
            for (int ks = 0; ks < 12; ks++) {
                uint32_t a[2][4], b[2][4];
#pragma unroll
                for (int mt = 0; mt < 2; mt++) {
                    uint32_t ad = aBase +
                        (uint32_t)((wm * 32 + mt * 16 + a_row) * (LDA2 * 2) +
                                   (ks * 16 + a_koff) * 2);
                    ldsm_x4(a[mt][0], a[mt][1], a[mt][2], a[mt][3], ad);
                }
#pragma unroll
                for (int np = 0; np < 2; np++) {
                    uint32_t bd = bBase +
                        (uint32_t)((wn * 32 + np * 16 + b_n) * (LDA2 * 2) +
                                   (ks * 16 + b_koff) * 2);
                    ldsm_x4(b[np][0], b[np][1], b[np][2], b[np][3], bd);
                }
#pragma unroll
                for (int mt = 0; mt < 2; mt++) {
#pragma unroll
                    for (int np = 0; np < 2; np++) {
                        uint32_t bfr0[2] = { b[np][0], b[np][2] };
                        uint32_t bfr1[2] = { b[np][1], b[np][3] };
                        mma_bf16(acc[mt][2 * np + 0], a[mt], bfr0);
                        mma_bf16(acc[mt][2 * np + 1], a[mt], bfr1);
                    }
                }
            }
        }
        // epilogue for this n-tile
#pragma unroll
        for (int mt = 0; mt < 2; mt++) {
            int mrow = m0 + wm * 32 + mt * 16 + r_in;
#pragma unroll
            for (int ntb = 0; ntb < 4; ntb++) {
                int col = n0 + wn * 32 + ntb * 8 + c_in;
#pragma unroll
                for (int e = 0; e < 4; e++) {
                    int rr = mrow + ((e >> 1) << 3);
                    int cc = col + (e & 1);
                    if (cc < Nvalid) {
                        float v = acc[mt][ntb][e] + bias[cc];
                        if (EPI == 0) {
                            Cf[(size_t)rr * ldc + cc] = v;
                        } else {
                            store_hilo(Chi, Clo, (size_t)rr * ldc + cc, gelu_f(v));
                        }
                    }
                }
            }
        }
    }
}

// ---------------- old per-tile GEMM (for fc2, Kpad=768), EPI=2 residual ----------------
#define LDA 72
#define SM_AHI 0
#define SM_ALO 18432
#define SM_BHI 36864
#define SM_BLO 46080
#define TC_SMEM_BYTES 55296

__global__ void __launch_bounds__(256) tc_gemm_res(
    const __nv_bfloat16* __restrict__ Ahi, const __nv_bfloat16* __restrict__ Alo,
    const __nv_bfloat16* __restrict__ Bhi, const __nv_bfloat16* __restrict__ Blo,
    const float* __restrict__ bias, const float* __restrict__ res,
    float* __restrict__ Cf, int Nvalid, int ldc, int Kpad, int nchunks) {
    extern __shared__ __align__(16) char sm[];
    const uint32_t smb = smem_u32(sm);
    const int tid = threadIdx.x;
    const int wid = tid >> 5, lane = tid & 31;
    const int wm = wid >> 1, wn = wid & 1;
    const int m0 = blockIdx.y * 128;
    const int n0 = blockIdx.x * 64;

    float acc[2][4][4] = {};
    const int a_row = lane & 15, a_koff = (lane >> 4) << 3;
    const int b_grp = lane >> 3, b_n = ((b_grp & 1) << 3) + (lane & 7), b_koff = (b_grp >> 1) << 3;

    for (int ch = 0; ch < nchunks; ch++) {
        const int k0 = ch * 64;
#pragma unroll
        for (int it = 0; it < 4; it++) {
            int c = tid + it * 256;
            int r = c >> 3, ko = (c & 7) << 3;
            size_t ga = (size_t)(m0 + r) * Kpad + k0 + ko;
            uint32_t so = r * (LDA * 2) + ko * 2;
            *(uint4*)(sm + SM_AHI + so) = *(const uint4*)(Ahi + ga);
            *(uint4*)(sm + SM_ALO + so) = *(const uint4*)(Alo + ga);
        }
#pragma unroll
        for (int it = 0; it < 2; it++) {
            int c = tid + it * 256;
            int r = c >> 3, ko = (c & 7) << 3;
            size_t gb = (size_t)(n0 + r) * Kpad + k0 + ko;
            uint32_t so = r * (LDA * 2) + ko * 2;
            *(uint4*)(sm + SM_BHI + so) = *(const uint4*)(Bhi + gb);
            *(uint4*)(sm + SM_BLO + so) = *(const uint4*)(Blo + gb);
        }
        __syncthreads();
#pragma unroll
        for (int pass = 0; pass < 3; pass++) {
            const uint32_t aBase = smb + (pass == 2 ? SM_ALO : SM_AHI);
            const uint32_t bBase = smb + (pass == 1 ? SM_BLO : SM_BHI);
#pragma unroll
            for (int ks = 0; ks < 4; ks++) {
                uint32_t a[2][4], b[2][4];
#pragma unroll
                for (int mt = 0; mt < 2; mt++) {
                    uint32_t ad = aBase +
                        (uint32_t)((wm * 32 + mt * 16 + a_row) * (LDA * 2) +
                                   (ks * 16 + a_koff) * 2);
                    ldsm_x4(a[mt][0], a[mt][1], a[mt][2], a[mt][3], ad);
                }
#pragma unroll
                for (int np = 0; np < 2; np++) {
                    uint32_t bd = bBase +
                        (uint32_t)((wn * 32 + np * 16 + b_n) * (LDA * 2) +
                                   (ks * 16 + b_koff) * 2);
                    ldsm_x4(b[np][0], b[np][1], b[np][2], b[np][3], bd);
                }
#pragma unroll
                for (int mt = 0; mt < 2; mt++) {
#pragma unroll
                    for (int np = 0; np < 2; np++) {
                        uint32_t bfr0[2] = { b[np][0], b[np][2] };
                        uint32_t bfr1[2] = { b[np][1], b[np][3] };
                        mma_bf16(acc[mt][2 * np + 0], a[mt], bfr0);
                        mma_bf16(acc[mt][2 * np + 1], a[mt], bfr1);
                    }
                }
            }
        }
        __syncthreads();
    }

    const int r_in = lane >> 2, c_in = (lane & 3) << 1;
#pragma unroll
    for (int mt = 0; mt < 2; mt++) {
        int mrow = m0 + wm * 32 + mt * 16 + r_in;
#pragma unroll
        for (int nt = 0; nt < 4; nt++) {
            int col = n0 + wn * 32 + nt * 8 + c_in;
#pragma unroll
            for (int e = 0; e < 4; e++) {
                int rr = mrow + ((e >> 1) << 3);
                int cc = col + (e & 1);
                if (cc < Nvalid) {
                    float v = acc[mt][nt][e] + bias[cc] + res[(size_t)rr * Nvalid + cc];
                    Cf[(size_t)rr * ldc + cc] = v;
                }
            }
        }
    }
}

// ---------------- conv1: implicit GEMM, padded bf16 in -> gelu -> padded bf16 out ----------------
__global__ void __launch_bounds__(256) conv1_tc(
    const __nv_bfloat16* __restrict__ xnp,
    const __nv_bfloat16* __restrict__ wh, const __nv_bfloat16* __restrict__ wl,
    const float* __restrict__ bias, __nv_bfloat16* __restrict__ y1p) {
    __shared__ __align__(16) __nv_bfloat16 sA[128 * LDA];
    __shared__ __align__(16) __nv_bfloat16 sBh[64 * LDA];
    __shared__ __align__(16) __nv_bfloat16 sBl[64 * LDA];
    const uint32_t sAu = smem_u32(sA), sBhu = smem_u32(sBh), sBlu = smem_u32(sBl);
    const int tid = threadIdx.x, wid = tid >> 5, lane = tid & 31;
    const int wm = wid >> 1, wn = wid & 1;
    const int tile = blockIdx.x;
    const int r = tile >> 1, c0 = (tile & 1) << 7;
    const int base = (r + 1) * PW + c0 + 1;
    const int a_row = lane & 15, a_koff = (lane >> 4) << 3;
    const int b_grp = lane >> 3, b_n = ((b_grp & 1) << 3) + (lane & 7), b_koff = (b_grp >> 1) << 3;
    float acc[2][4][4] = {};

    for (int tap = 0; tap < 9; tap++) {
        int dy = tap / 3 - 1, dx = tap % 3 - 1;
        int off = dy * PW + dx;
        for (int ch = 0; ch < 3; ch++) {
            __syncthreads();
#pragma unroll
            for (int it = 0; it < 4; it++) {
                int c = tid + it * 256;
                int rr = c >> 3, ko = (c & 7) << 3;
                *(uint4*)(sA + rr * LDA + ko) =
                    *(const uint4*)(xnp + (size_t)(base + off + rr) * KP1 + ch * 64 + ko);
            }
#pragma unroll
            for (int it = 0; it < 2; it++) {
                int c = tid + it * 256;
                int rr = c >> 3, ko = (c & 7) << 3;
                size_t gb = (size_t)(tap * 64 + rr) * KP1 + ch * 64 + ko;
                *(uint4*)(sBh + rr * LDA + ko) = *(const uint4*)(wh + gb);
                *(uint4*)(sBl + rr * LDA + ko) = *(const uint4*)(wl + gb);
            }
            __syncthreads();
#pragma unroll
            for (int pass = 0; pass < 2; pass++) {
                const uint32_t bBase = pass ? sBlu : sBhu;
#pragma unroll
                for (int ks = 0; ks < 4; ks++) {
                    uint32_t a[2][4], b[2][4];
#pragma unroll
                    for (int mt = 0; mt < 2; mt++) {
                        uint32_t ad = sAu +
                            (uint32_t)((wm * 32 + mt * 16 + a_row) * (LDA * 2) +
                                       (ks * 16 + a_koff) * 2);
                        ldsm_x4(a[mt][0], a[mt][1], a[mt][2], a[mt][3], ad);
                    }
#pragma unroll
                    for (int np = 0; np < 2; np++) {
                        uint32_t bd = bBase +
                            (uint32_t)((wn * 32 + np * 16 + b_n) * (LDA * 2) +
                                       (ks * 16 + b_koff) * 2);
                        ldsm_x4(b[np][0], b[np][1], b[np][2], b[np][3], bd);
                    }
#pragma unroll
                    for (int mt = 0; mt < 2; mt++) {
#pragma unroll
                        for (int np = 0; np < 2; np++) {
                            uint32_t bfr0[2] = { b[np][0], b[np][2] };
                            uint32_t bfr1[2] = { b[np][1], b[np][3] };
                            mma_bf16(acc[mt][2 * np + 0], a[mt], bfr0);
                            mma_bf16(acc[mt][2 * np + 1], a[mt], bfr1);
                        }
                    }
                }
            }
        }
    }

    const int r_in = lane >> 2, c_in = (lane & 3) << 1;
#pragma unroll
    for (int mt = 0; mt < 2; mt++) {
        int rowbase = wm * 32 + mt * 16 + r_in;
#pragma unroll
        for (int nt = 0; nt < 4; nt++) {
            int col = wn * 32 + nt * 8 + c_in;
#pragma unroll
            for (int e = 0; e < 4; e++) {
                int rit = rowbase + ((e >> 1) << 3);
                int cc = col + (e & 1);
                float bb = (cc < 60) ? bias[cc] : 0.f;
                float v = gelu_f(acc[mt][nt][e] + bb);
                y1p[(size_t)(base + rit) * 64 + cc] = __float2bfloat16(v);
            }
        }
    }
}

// ---------------- conv2: implicit GEMM, padded bf16 in -> y2 fp32 [NP][180] ----------------
__global__ void __launch_bounds__(256) conv2_tc(
    const __nv_bfloat16* __restrict__ y1p,
    const __nv_bfloat16* __restrict__ wh, const __nv_bfloat16* __restrict__ wl,
    const float* __restrict__ bias, float* __restrict__ y2) {
    __shared__ __align__(16) __nv_bfloat16 sA[128 * LDA];
    __shared__ __align__(16) __nv_bfloat16 sBh[64 * LDA];
    __shared__ __align__(16) __nv_bfloat16 sBl[64 * LDA];
    const uint32_t sAu = smem_u32(sA), sBhu = smem_u32(sBh), sBlu = smem_u32(sBl);
    const int tid = threadIdx.x, wid = tid >> 5, lane = tid & 31;
    const int wm = wid >> 1, wn = wid & 1;
    const int n0 = blockIdx.x * 64;
    const int tile = blockIdx.y;
    const int r = tile >> 1, c0 = (tile & 1) << 7;
    const int base = (r + 1) * PW + c0 + 1;
    const int a_row = lane & 15, a_koff = (lane >> 4) << 3;
    const int b_grp = lane >> 3, b_n = ((b_grp & 1) << 3) + (lane & 7), b_koff = (b_grp >> 1) << 3;
    float acc[2][4][4] = {};

    for (int tap = 0; tap < 9; tap++) {
        int dy = tap / 3 - 1, dx = tap % 3 - 1;
        int off = dy * PW + dx;
        __syncthreads();
#pragma unroll
        for (int it = 0; it < 4; it++) {
            int c = tid + it * 256;
            int rr = c >> 3, ko = (c & 7) << 3;
            *(uint4*)(sA + rr * LDA + ko) =
                *(const uint4*)(y1p + (size_t)(base + off + rr) * 64 + ko);
        }
#pragma unroll
        for (int it = 0; it < 2; it++) {
            int c = tid + it * 256;
            int rr = c >> 3, ko = (c & 7) << 3;
            size_t gb = (size_t)(tap * 192 + n0 + rr) * 64 + ko;
            *(uint4*)(sBh + rr * LDA + ko) = *(const uint4*)(wh + gb);
            *(uint4*)(sBl + rr * LDA + ko) = *(const uint4*)(wl + gb);
        }
        __syncthreads();
#pragma unroll
        for (int pass = 0; pass < 2; pass++) {
            const uint32_t bBase = pass ? sBlu : sBhu;
#pragma unroll
            for (int ks = 0; ks < 4; ks++) {
                uint32_t a[2][4], b[2][4];
#pragma unroll
                for (int mt = 0; mt < 2; mt++) {
                    uint32_t ad = sAu +
                        (uint32_t)((wm * 32 + mt * 16 + a_row) * (LDA * 2) +
                                   (ks * 16 + a_koff) * 2);
                    ldsm_x4(a[mt][0], a[mt][1], a[mt][2], a[mt][3], ad);
                }
#pragma unroll
                for (int np = 0; np < 2; np++) {
                    uint32_t bd = bBase +
                        (uint32_t)((wn * 32 + np * 16 + b_n) * (LDA * 2) +
                                   (ks * 16 + b_koff) * 2);
                    ldsm_x4(b[np][0], b[np][1], b[np][2], b[np][3], bd);
                }
#pragma unroll
                for (int mt = 0; mt < 2; mt++) {
#pragma unroll
                    for (int np = 0; np < 2; np++) {
                        uint32_t bfr0[2] = { b[np][0], b[np][2] };
                        uint32_t bfr1[2] = { b[np][1], b[np][3] };
                        mma_bf16(acc[mt][2 * np + 0], a[mt], bfr0);
                        mma_bf16(acc[mt][2 * np + 1], a[mt], bfr1);
                    }
                }
            }
        }
    }

    const int r_in = lane >> 2, c_in = (lane & 3) << 1;
#pragma unroll
    for (int mt = 0; mt < 2; mt++) {
        int rowbase = wm * 32 + mt * 16 + r_in;
#pragma unroll
        for (int nt = 0; nt < 4; nt++) {
            int col = n0 + wn * 32 + nt * 8 + c_in;
#pragma unroll
            for (int e = 0; e < 4; e++) {
                int rit = rowbase + ((e >> 1) << 3);
                int cc = col + (e & 1);
                if (cc < CDIM) {
                    int p = r * 256 + c0 + rit;
                    y2[(size_t)p * CDIM + cc] = acc[mt][nt][e] + bias[cc];
                }
            }
        }
    }
}

// ---------------- LayerNorm (one warp per token); also writes padded bf16 image ----------------
__global__ void ln_kernel(const float* __restrict__ x, const float* __restrict__ g,
                          const float* __restrict__ b, float* __restrict__ out,
                          __nv_bfloat16* __restrict__ xnp) {
    int p = blockIdx.x * 8 + (threadIdx.x >> 5);
    int lane = threadIdx.x & 31;
    const float* xr = x + (size_t)p * CDIM;
    float v[6];
    float s = 0.f;
#pragma unroll
    for (int k = 0; k < 6; k++) {
        int c = k * 32 + lane;
        v[k] = (c < CDIM) ? xr[c] : 0.f;
        s += v[k];
    }
    s = warp_sum(s);
    float mu = s * (1.0f / CDIM);
    float sq = 0.f;
#pragma unroll
    for (int k = 0; k < 6; k++) {
        int c = k * 32 + lane;
        if (c < CDIM) { float d = v[k] - mu; sq += d * d; }
    }
    sq = warp_sum(sq);
    float rstd = rsqrtf(sq * (1.0f / CDIM) + 1e-5f);
    float* orow = out + (size_t)p * CDIM;
    int rr = p >> 8, cc = p & 255;
    size_t pidx = (size_t)((rr + 1) * PW + cc + 1) * KP1;
#pragma unroll
    for (int k = 0; k < 6; k++) {
        int c = k * 32 + lane;
        if (c < CDIM) {
            float y = (v[k] - mu) * rstd * g[c] + b[c];
            orow[c] = y;
            xnp[pidx + c] = __float2bfloat16(y);
        }
    }
}

// ---------------- roll + window gather -> bf16 hi/lo A ----------------
__global__ void gather_kernel(const float* __restrict__ xn,
                              __nv_bfloat16* __restrict__ ah, __nv_bfloat16* __restrict__ al) {
    int widx = blockIdx.x;
    int c = threadIdx.x;
    if (c >= CDIM) return;
    int win = widx >> 8, tok = widx & 255;
    int hs = ((win >> 4) << 4) + (tok >> 4);
    int ws2 = ((win & 15) << 4) + (tok & 15);
    int hr = (hs + 8) & 255;
    int wr = (ws2 + 8) & 255;
    float v = xn[(size_t)(hr * 256 + wr) * CDIM + c];
    store_hilo(ah, al, (size_t)widx * KP1 + c, v);
}

// ---------------- relative position bias ----------------
__global__ void rpb_kernel(const int* __restrict__ rpi, const float* __restrict__ table,
                           float* __restrict__ rpb) {
    int idx = blockIdx.x * 256 + threadIdx.x;
    int r = rpi[idx];
#pragma unroll
    for (int h = 0; h < NHEADS; h++) rpb[h * 65536 + idx] = table[r * NHEADS + h];
}

// ---------------- channel-attention pooling ----------------
__global__ void pool_kernel(const float* __restrict__ y2, float* __restrict__ casum) {
    int c = threadIdx.x;
    if (c >= CDIM) return;
    int p0 = blockIdx.x * 256;
    float s = 0.f;
    for (int i = 0; i < 256; i++) s += y2[(size_t)(p0 + i) * CDIM + c];
    atomicAdd(&casum[c], s);
}

__global__ void ca_kernel(const float* __restrict__ casum,
                          const float* __restrict__ w1, const float* __restrict__ b1,
                          const float* __restrict__ w2, const float* __restrict__ b2,
                          float* __restrict__ ca) {
    __shared__ float mean[CDIM];
    __shared__ float sq[6];
    int t = threadIdx.x;
    if (t < CDIM) mean[t] = casum[t] * (1.0f / NP);
    __syncthreads();
    if (t < 6) {
        float a = b1[t];
        for (int c = 0; c < CDIM; c++) a += mean[c] * w1[t * CDIM + c];
        sq[t] = fmaxf(a, 0.f);
    }
    __syncthreads();
    if (t < CDIM) {
        float a = b2[t];
#pragma unroll
        for (int s = 0; s < 6; s++) a += sq[s] * w2[t * 6 + s];
        ca[t] = 1.0f / (1.0f + __expf(-a));
    }
}

// ---------------- flash attention per (window, head), writes bf16 hi/lo ----------------
__global__ void __launch_bounds__(256) attn_kernel(const float* __restrict__ qkv,
                                                   const float* __restrict__ rpb,
                                                   const float* __restrict__ mask,
                                                   __nv_bfloat16* __restrict__ oh,
                                                   __nv_bfloat16* __restrict__ ol) {
    int win = blockIdx.x;
    int head = blockIdx.y;
    __shared__ float ks[32][30];
    __shared__ float vs[32][30];
    int qi = threadIdx.x;
    int base = win * 256;
    const float* qp = qkv + (size_t)(base + qi) * 540 + head * HD;
    float q[HD];
#pragma unroll
    for (int d = 0; d < HD; d++) q[d] = qp[d] * 0.18257418583505536f;
    float o[HD];
#pragma unroll
    for (int d = 0; d < HD; d++) o[d] = 0.f;
    float mx = -1e30f, l = 0.f;
    const float* rb = rpb + (size_t)head * 65536 + qi * 256;
    const float* mk = mask + (size_t)win * 65536 + qi * 256;
    for (int kt = 0; kt < 8; kt++) {
        __syncthreads();
        for (int idx = threadIdx.x; idx < 32 * HD; idx += 256) {
            int j = idx / HD, d = idx % HD;
            size_t tok = (size_t)(base + kt * 32 + j) * 540;
            ks[j][d] = qkv[tok + 180 + head * HD + d];
            vs[j][d] = qkv[tok + 360 + head * HD + d];
        }
        __syncthreads();
        float s[32];
        float cm = -1e30f;
#pragma unroll
        for (int j = 0; j < 32; j++) {
            float a = 0.f;
#pragma unroll
            for (int d2 = 0; d2 < 15; d2++) {
                float2 kv = *(const float2*)&ks[j][d2 * 2];
                a += q[d2 * 2] * kv.x + q[d2 * 2 + 1] * kv.y;
            }
            s[j] = a + rb[kt * 32 + j] + mk[kt * 32 + j];
            cm = fmaxf(cm, s[j]);
        }
        float nm = fmaxf(mx, cm);
        float corr = __expf(mx - nm);
        l *= corr;
#pragma unroll
        for (int d = 0; d < HD; d++) o[d] *= corr;
#pragma unroll
        for (int j = 0; j < 32; j++) {
            float p = __expf(s[j] - nm);
            l += p;
#pragma unroll
            for (int d2 = 0; d2 < 15; d2++) {
                float2 vv = *(const float2*)&vs[j][d2 * 2];
                o[d2 * 2] += p * vv.x;
                o[d2 * 2 + 1] += p * vv.y;
            }
        }
        mx = nm;
    }
    float inv = 1.0f / l;
    size_t ob = (size_t)(base + qi) * KP1 + head * HD;
#pragma unroll
    for (int d = 0; d < HD; d++) store_hilo(oh, ol, ob + d, o[d] * inv);
}

// ---------------- residual combine + LN2: x1 fp32 + xm hi/lo ----------------
__global__ void combine_ln2(const float* __restrict__ x, const float* __restrict__ proj,
                            const float* __restrict__ y2, const float* __restrict__ ca,
                            const float* __restrict__ g2, const float* __restrict__ b2,
                            float* __restrict__ x1,
                            __nv_bfloat16* __restrict__ mh, __nv_bfloat16* __restrict__ ml) {
    int p = blockIdx.x * 8 + (threadIdx.x >> 5);
    int lane = threadIdx.x & 31;
    int r = p >> 8, cc = p & 255;
    int hs = (r + 248) & 255;
    int ws2 = (cc + 248) & 255;
    int widx = (((hs >> 4) << 4) + (ws2 >> 4)) * 256 + ((hs & 15) << 4) + (ws2 & 15);
    float v[6];
    float s = 0.f;
#pragma unroll
    for (int k = 0; k < 6; k++) {
        int c = k * 32 + lane;
        if (c < CDIM) {
            v[k] = x[(size_t)p * CDIM + c] + proj[(size_t)widx * CDIM + c]
                 + 0.01f * y2[(size_t)p * CDIM + c] * ca[c];
        } else v[k] = 0.f;
        s += v[k];
    }
    s = warp_sum(s);
    float mu = s * (1.0f / CDIM);
    float sq = 0.f;
#pragma unroll
    for (int k = 0; k < 6; k++) {
        int c = k * 32 + lane;
        if (c < CDIM) { float d = v[k] - mu; sq += d * d; }
    }
    sq = warp_sum(sq);
    float rstd = rsqrtf(sq * (1.0f / CDIM) + 1e-5f);
#pragma unroll
    for (int k = 0; k < 6; k++) {
        int c = k * 32 + lane;
        if (c < CDIM) {
            x1[(size_t)p * CDIM + c] = v[k];
            store_hilo(mh, ml, (size_t)p * KP1 + c, (v[k] - mu) * rstd * g2[c] + b2[c]);
        }
    }
}

// ---------------- launcher ----------------
extern "C" void kernel_launch(void* const* d_in, const int* in_sizes, int n_in,
                              void* d_out, int out_size) {
    const float* x     = (const float*)d_in[0];
    const int*   rpi   = (const int*)d_in[3];
    const float* mask  = (const float*)d_in[4];
    const float* n1g   = (const float*)d_in[5];
    const float* n1b   = (const float*)d_in[6];
    const float* qkvw  = (const float*)d_in[7];
    const float* qkvb  = (const float*)d_in[8];
    const float* rpbt  = (const float*)d_in[9];
    const float* projw = (const float*)d_in[10];
    const float* projb = (const float*)d_in[11];
    const float* c1w   = (const float*)d_in[12];
    const float* c1b   = (const float*)d_in[13];
    const float* c2w   = (const float*)d_in[14];
    const float* c2b   = (const float*)d_in[15];
    const float* ca1w  = (const float*)d_in[16];
    const float* ca1b  = (const float*)d_in[17];
    const float* ca2w  = (const float*)d_in[18];
    const float* ca2b  = (const float*)d_in[19];
    const float* n2g   = (const float*)d_in[20];
    const float* n2b   = (const float*)d_in[21];
    const float* f1w   = (const float*)d_in[22];
    const float* f1b   = (const float*)d_in[23];
    const float* f2w   = (const float*)d_in[24];
    const float* f2b   = (const float*)d_in[25];
    float* out = (float*)d_out;

    float *xn, *qkv, *proj, *y2, *rpb, *casum, *ca, *x1;
    __nv_bfloat16 *xnp, *y1p, *ahi, *alo, *mhi, *mlo;
    __nv_bfloat16 *bqh, *bql, *bph, *bpl, *b1h, *b1l, *b2h, *b2l;
    __nv_bfloat16 *wc1h, *wc1l, *wc2h, *wc2l;
    cudaGetSymbolAddress((void**)&xn, g_xn);
    cudaGetSymbolAddress((void**)&qkv, g_qkv);
    cudaGetSymbolAddress((void**)&proj, g_proj);
    cudaGetSymbolAddress((void**)&y2, g_y2);
    cudaGetSymbolAddress((void**)&rpb, g_rpb);
    cudaGetSymbolAddress((void**)&casum, g_casum);
    cudaGetSymbolAddress((void**)&ca, g_ca);
    cudaGetSymbolAddress((void**)&x1, g_x1);
    cudaGetSymbolAddress((void**)&xnp, g_xnp);
    cudaGetSymbolAddress((void**)&y1p, g_y1p);
    cudaGetSymbolAddress((void**)&ahi, g_ahi);
    cudaGetSymbolAddress((void**)&alo, g_alo);
    cudaGetSymbolAddress((void**)&mhi, g_mhi);
    cudaGetSymbolAddress((void**)&mlo, g_mlo);
    cudaGetSymbolAddress((void**)&bqh, g_bqh);
    cudaGetSymbolAddress((void**)&bql, g_bql);
    cudaGetSymbolAddress((void**)&bph, g_bph);
    cudaGetSymbolAddress((void**)&bpl, g_bpl);
    cudaGetSymbolAddress((void**)&b1h, g_b1h);
    cudaGetSymbolAddress((void**)&b1l, g_b1l);
    cudaGetSymbolAddress((void**)&b2h, g_b2h);
    cudaGetSymbolAddress((void**)&b2l, g_b2l);
    cudaGetSymbolAddress((void**)&wc1h, g_wc1h);
    cudaGetSymbolAddress((void**)&wc1l, g_wc1l);
    cudaGetSymbolAddress((void**)&wc2h, g_wc2h);
    cudaGetSymbolAddress((void**)&wc2l, g_wc2l);

    cudaFuncSetAttribute(tc_gemm2<0>, cudaFuncAttributeMaxDynamicSharedMemorySize, G2_SMEM);
    cudaFuncSetAttribute(tc_gemm2<1>, cudaFuncAttributeMaxDynamicSharedMemorySize, G2_SMEM);
    cudaFuncSetAttribute(tc_gemm_res, cudaFuncAttributeMaxDynamicSharedMemorySize, TC_SMEM_BYTES);

    // weight prep (tiny)
    prepb_kernel<<<432, 256>>>(qkvw, 180, 540, KP1, 576, bqh, bql);
    prepb_kernel<<<144, 256>>>(projw, 180, 180, KP1, 192, bph, bpl);
    prepb_kernel<<<576, 256>>>(f1w, 180, 720, KP1, 768, b1h, b1l);
    prepb_kernel<<<576, 256>>>(f2w, 720, 180, KP2, 192, b2h, b2l);
    prepc1_kernel<<<432, 256>>>(c1w, wc1h, wc1l);
    prepc2_kernel<<<432, 256>>>(c2w, wc2h, wc2l);

    ln_kernel<<<NP / 8, 256>>>(x, n1g, n1b, xn, xnp);
    gather_kernel<<<NP, 192>>>(xn, ahi, alo);
    rpb_kernel<<<256, 256>>>(rpi, rpbt, rpb);

    // qkv projection + attention + proj
    tc_gemm2<0><<<512, 256, G2_SMEM>>>(ahi, alo, bqh, bql, qkvb, qkv, nullptr, nullptr,
                                       540, 540, 9);
    attn_kernel<<<dim3(256, 6), 256>>>(qkv, rpb, mask, ahi, alo);
    tc_gemm2<0><<<512, 256, G2_SMEM>>>(ahi, alo, bph, bpl, projb, proj, nullptr, nullptr,
                                       180, 180, 3);

    // conv branch (tensor core implicit GEMM)
    conv1_tc<<<512, 256>>>(xnp, wc1h, wc1l, c1b, y1p);
    conv2_tc<<<dim3(3, 512), 256>>>(y1p, wc2h, wc2l, c2b, y2);
    cudaMemsetAsync(casum, 0, CDIM * sizeof(float));
    pool_kernel<<<256, 192>>>(y2, casum);
    ca_kernel<<<1, 192>>>(casum, ca1w, ca1b, ca2w, ca2b, ca);

    // combine + LN2 + MLP
    combine_ln2<<<NP / 8, 256>>>(x, proj, y2, ca, n2g, n2b, x1, ahi, alo);
    tc_gemm2<1><<<512, 256, G2_SMEM>>>(ahi, alo, b1h, b1l, f1b, nullptr, mhi, mlo,
                                       720, 768, 12);
    tc_gemm_res<<<dim3(3, 512), 256, TC_SMEM_BYTES>>>(mhi, mlo, b2h, b2l, f2b, x1, out,
                                                      180, 180, KP2, 12);
}

// round 5
// speedup vs baseline: 2.3811x; 1.4812x over previous
#include <cuda_runtime.h>
#include <cuda_bf16.h>
#include <math.h>
#include <stdint.h>

#define NP 65536
#define CDIM 180
#define NHEADS 6
#define HD 30
#define HID 720
#define KP1 192
#define KP2 768
#define PW 258   // padded image width/height

// ---------------- scratch (device globals; no allocations) ----------------
__device__ __align__(16) float g_xn[NP * CDIM];
__device__ __align__(16) float g_qkv[NP * 540];
__device__ __align__(16) float g_proj[NP * CDIM];
__device__ __align__(16) float g_y2[NP * CDIM];
__device__ __align__(16) __nv_bfloat16 g_rpbb[NHEADS * 65536];
__device__ __align__(16) __nv_bfloat16 g_maskb[256 * 65536];
__device__ float g_casum[CDIM];
__device__ float g_ca[CDIM];
__device__ __align__(16) float g_x1[NP * CDIM];
// padded bf16 image for conv branch (halo stays zero forever)
__device__ __align__(16) __nv_bfloat16 g_xnp[PW * PW * KP1];
__device__ __align__(16) __nv_bfloat16 g_y1p[PW * PW * 64];
// bf16 split activations (zero-initialized; K-pad columns stay zero forever)
__device__ __align__(16) __nv_bfloat16 g_ahi[NP * KP1];
__device__ __align__(16) __nv_bfloat16 g_alo[NP * KP1];
__device__ __align__(16) __nv_bfloat16 g_mhi[NP * KP2];
__device__ __align__(16) __nv_bfloat16 g_mlo[NP * KP2];
// bf16 split transposed weights [N_pad][K_pad]
__device__ __align__(16) __nv_bfloat16 g_bqh[576 * KP1], g_bql[576 * KP1];
__device__ __align__(16) __nv_bfloat16 g_bph[192 * KP1], g_bpl[192 * KP1];
__device__ __align__(16) __nv_bfloat16 g_b1h[768 * KP1], g_b1l[768 * KP1];
__device__ __align__(16) __nv_bfloat16 g_b2h[192 * KP2], g_b2l[192 * KP2];
// conv weights: [tap][ocpad][kpad]
__device__ __align__(16) __nv_bfloat16 g_wc1h[9 * 64 * KP1], g_wc1l[9 * 64 * KP1];
__device__ __align__(16) __nv_bfloat16 g_wc2h[9 * 192 * 64], g_wc2l[9 * 192 * 64];

__device__ __forceinline__ float gelu_f(float x) {
    return 0.5f * x * (1.0f + erff(x * 0.70710678118654752f));
}
__device__ __forceinline__ float warp_sum(float v) {
    for (int o = 16; o > 0; o >>= 1) v += __shfl_xor_sync(0xffffffffu, v, o);
    return v;
}
__device__ __forceinline__ void store_hilo(__nv_bfloat16* h, __nv_bfloat16* l,
                                           size_t idx, float v) {
    __nv_bfloat16 hh = __float2bfloat16(v);
    h[idx] = hh;
    l[idx] = __float2bfloat16(v - __bfloat162float(hh));
}
__device__ __forceinline__ uint32_t smem_u32(const void* p) {
    uint32_t a;
    asm("{ .reg .u64 t; cvta.to.shared.u64 t, %1; cvt.u32.u64 %0, t; }" : "=r"(a) : "l"(p));
    return a;
}
__device__ __forceinline__ void ldsm_x4(uint32_t& r0, uint32_t& r1, uint32_t& r2, uint32_t& r3,
                                        uint32_t addr) {
    asm volatile("ldmatrix.sync.aligned.m8n8.x4.shared.b16 {%0,%1,%2,%3}, [%4];"
                 : "=r"(r0), "=r"(r1), "=r"(r2), "=r"(r3) : "r"(addr));
}
__device__ __forceinline__ void mma_bf16(float* c, const uint32_t* a, const uint32_t* b) {
    asm volatile(
        "mma.sync.aligned.m16n8k16.row.col.f32.bf16.bf16.f32 "
        "{%0,%1,%2,%3}, {%4,%5,%6,%7}, {%8,%9}, {%0,%1,%2,%3};"
        : "+f"(c[0]), "+f"(c[1]), "+f"(c[2]), "+f"(c[3])
        : "r"(a[0]), "r"(a[1]), "r"(a[2]), "r"(a[3]), "r"(b[0]), "r"(b[1]));
}
__device__ __forceinline__ void split2(float a, float b, uint32_t& hi, uint32_t& lo) {
    __nv_bfloat16 ah = __float2bfloat16(a), bh = __float2bfloat16(b);
    __nv_bfloat162 h2; h2.x = ah; h2.y = bh;
    hi = *(uint32_t*)&h2;
    __nv_bfloat162 l2;
    l2.x = __float2bfloat16(a - __bfloat162float(ah));
    l2.y = __float2bfloat16(b - __bfloat162float(bh));
    lo = *(uint32_t*)&l2;
}

// ---------------- weight prep: W[K,N] -> hi/lo [N_pad,K_pad] ----------------
__global__ void prepb_kernel(const float* __restrict__ W, int K, int N, int K_pad, int N_pad,
                             __nv_bfloat16* __restrict__ bh, __nv_bfloat16* __restrict__ bl) {
    int idx = blockIdx.x * 256 + threadIdx.x;
    if (idx >= N_pad * K_pad) return;
    int n = idx / K_pad, k = idx % K_pad;
    float v = (n < N && k < K) ? W[k * N + n] : 0.f;
    __nv_bfloat16 h = __float2bfloat16(v);
    bh[idx] = h;
    bl[idx] = __float2bfloat16(v - __bfloat162float(h));
}

__global__ void prepc1_kernel(const float* __restrict__ W,
                              __nv_bfloat16* __restrict__ bh, __nv_bfloat16* __restrict__ bl) {
    int idx = blockIdx.x * 256 + threadIdx.x;
    if (idx >= 9 * 64 * KP1) return;
    int k = idx % KP1;
    int rest = idx / KP1;
    int oc = rest % 64, tap = rest / 64;
    float v = (oc < 60 && k < 180) ? W[(oc * 180 + k) * 9 + tap] : 0.f;
    __nv_bfloat16 h = __float2bfloat16(v);
    bh[idx] = h;
    bl[idx] = __float2bfloat16(v - __bfloat162float(h));
}

__global__ void prepc2_kernel(const float* __restrict__ W,
                              __nv_bfloat16* __restrict__ bh, __nv_bfloat16* __restrict__ bl) {
    int idx = blockIdx.x * 256 + threadIdx.x;
    if (idx >= 9 * 192 * 64) return;
    int k = idx % 64;
    int rest = idx / 64;
    int oc = rest % 192, tap = rest / 192;
    float v = (oc < 180 && k < 60) ? W[(oc * 60 + k) * 9 + tap] : 0.f;
    __nv_bfloat16 h = __float2bfloat16(v);
    bh[idx] = h;
    bl[idx] = __float2bfloat16(v - __bfloat162float(h));
}

// ---------------- persistent-A HMMA GEMM (Kpad = 192) ----------------
#define LDA2 200
#define G2_SMEM (128 * LDA2 * 2 * 2 + 64 * LDA2 * 2 * 2)

template <int EPI>
__global__ void __launch_bounds__(256) tc_gemm2(
    const __nv_bfloat16* __restrict__ Ahi, const __nv_bfloat16* __restrict__ Alo,
    const __nv_bfloat16* __restrict__ Bhi, const __nv_bfloat16* __restrict__ Blo,
    const float* __restrict__ bias,
    float* __restrict__ Cf, __nv_bfloat16* __restrict__ Chi, __nv_bfloat16* __restrict__ Clo,
    int Nvalid, int ldc, int ntiles) {
    extern __shared__ __align__(16) char sm2[];
    __nv_bfloat16* sAh = (__nv_bfloat16*)sm2;
    __nv_bfloat16* sAl = sAh + 128 * LDA2;
    __nv_bfloat16* sBh = sAl + 128 * LDA2;
    __nv_bfloat16* sBl = sBh + 64 * LDA2;
    const uint32_t sAhu = smem_u32(sAh), sAlu = smem_u32(sAl);
    const uint32_t sBhu = smem_u32(sBh), sBlu = smem_u32(sBl);
    const int tid = threadIdx.x, wid = tid >> 5, lane = tid & 31;
    const int wm = wid >> 1, wn = wid & 1;
    const int m0 = blockIdx.x * 128;
    const int a_row = lane & 15, a_koff = (lane >> 4) << 3;
    const int b_grp = lane >> 3, b_n = ((b_grp & 1) << 3) + (lane & 7), b_koff = (b_grp >> 1) << 3;
    const int r_in = lane >> 2, c_in = (lane & 3) << 1;

#pragma unroll
    for (int it = 0; it < 12; it++) {
        int c = tid + it * 256;
        int rr = c / 24, ko = (c % 24) * 8;
        size_t ga = (size_t)(m0 + rr) * KP1 + ko;
        *(uint4*)(sAh + rr * LDA2 + ko) = *(const uint4*)(Ahi + ga);
        *(uint4*)(sAl + rr * LDA2 + ko) = *(const uint4*)(Alo + ga);
    }

    for (int nt = 0; nt < ntiles; nt++) {
        const int n0 = nt * 64;
        __syncthreads();
#pragma unroll
        for (int it = 0; it < 6; it++) {
            int c = tid + it * 256;
            int rr = c / 24, ko = (c % 24) * 8;
            size_t gb = (size_t)(n0 + rr) * KP1 + ko;
            *(uint4*)(sBh + rr * LDA2 + ko) = *(const uint4*)(Bhi + gb);
            *(uint4*)(sBl + rr * LDA2 + ko) = *(const uint4*)(Blo + gb);
        }
        __syncthreads();

        float acc[2][4][4] = {};
#pragma unroll
        for (int pass = 0; pass < 3; pass++) {
            const uint32_t aBase = (pass == 2) ? sAlu : sAhu;
            const uint32_t bBase = (pass == 1) ? sBlu : sBhu;
#pragma unroll
            for (int ks = 0; ks < 12; ks++) {
                uint32_t a[2][4], b[2][4];
#pragma unroll
                for (int mt = 0; mt < 2; mt++) {
                    uint32_t ad = aBase +
                        (uint32_t)((wm * 32 + mt * 16 + a_row) * (LDA2 * 2) +
                                   (ks * 16 + a_koff) * 2);
                    ldsm_x4(a[mt][0], a[mt][1], a[mt][2], a[mt][3], ad);
                }
#pragma unroll
                for (int np = 0; np < 2; np++) {
                    uint32_t bd = bBase +
                        (uint32_t)((wn * 32 + np * 16 + b_n) * (LDA2 * 2) +
                                   (ks * 16 + b_koff) * 2);
                    ldsm_x4(b[np][0], b[np][1], b[np][2], b[np][3], bd);
                }
#pragma unroll
                for (int mt = 0; mt < 2; mt++) {
#pragma unroll
                    for (int np = 0; np < 2; np++) {
                        uint32_t bfr0[2] = { b[np][0], b[np][2] };
                        uint32_t bfr1[2] = { b[np][1], b[np][3] };
                        mma_bf16(acc[mt][2 * np + 0], a[mt], bfr0);
                        mma_bf16(acc[mt][2 * np + 1], a[mt], bfr1);
                    }
                }
            }
        }
#pragma unroll
        for (int mt = 0; mt < 2; mt++) {
            int mrow = m0 + wm * 32 + mt * 16 + r_in;
#pragma unroll
            for (int ntb = 0; ntb < 4; ntb++) {
                int col = n0 + wn * 32 + ntb * 8 + c_in;
#pragma unroll
                for (int e = 0; e < 4; e++) {
                    int rr = mrow + ((e >> 1) << 3);
                    int cc = col + (e & 1);
                    if (cc < Nvalid) {
                        float v = acc[mt][ntb][e] + bias[cc];
                        if (EPI == 0) {
                            Cf[(size_t)rr * ldc + cc] = v;
                        } else {
                            store_hilo(Chi, Clo, (size_t)rr * ldc + cc, gelu_f(v));
                        }
                    }
                }
            }
        }
    }
}

// ---------------- per-tile GEMM (fc2, Kpad=768), bias+residual ----------------
#define LDA 72
#define SM_AHI 0
#define SM_ALO 18432
#define SM_BHI 36864
#define SM_BLO 46080
#define TC_SMEM_BYTES 55296

__global__ void __launch_bounds__(256) tc_gemm_res(
    const __nv_bfloat16* __restrict__ Ahi, const __nv_bfloat16* __restrict__ Alo,
    const __nv_bfloat16* __restrict__ Bhi, const __nv_bfloat16* __restrict__ Blo,
    const float* __restrict__ bias, const float* __restrict__ res,
    float* __restrict__ Cf, int Nvalid, int ldc, int Kpad, int nchunks) {
    extern __shared__ __align__(16) char sm[];
    const uint32_t smb = smem_u32(sm);
    const int tid = threadIdx.x;
    const int wid = tid >> 5, lane = tid & 31;
    const int wm = wid >> 1, wn = wid & 1;
    const int m0 = blockIdx.y * 128;
    const int n0 = blockIdx.x * 64;

    float acc[2][4][4] = {};
    const int a_row = lane & 15, a_koff = (lane >> 4) << 3;
    const int b_grp = lane >> 3, b_n = ((b_grp & 1) << 3) + (lane & 7), b_koff = (b_grp >> 1) << 3;

    for (int ch = 0; ch < nchunks; ch++) {
        const int k0 = ch * 64;
#pragma unroll
        for (int it = 0; it < 4; it++) {
            int c = tid + it * 256;
            int r = c >> 3, ko = (c & 7) << 3;
            size_t ga = (size_t)(m0 + r) * Kpad + k0 + ko;
            uint32_t so = r * (LDA * 2) + ko * 2;
            *(uint4*)(sm + SM_AHI + so) = *(const uint4*)(Ahi + ga);
            *(uint4*)(sm + SM_ALO + so) = *(const uint4*)(Alo + ga);
        }
#pragma unroll
        for (int it = 0; it < 2; it++) {
            int c = tid + it * 256;
            int r = c >> 3, ko = (c & 7) << 3;
            size_t gb = (size_t)(n0 + r) * Kpad + k0 + ko;
            uint32_t so = r * (LDA * 2) + ko * 2;
            *(uint4*)(sm + SM_BHI + so) = *(const uint4*)(Bhi + gb);
            *(uint4*)(sm + SM_BLO + so) = *(const uint4*)(Blo + gb);
        }
        __syncthreads();
#pragma unroll
        for (int pass = 0; pass < 3; pass++) {
            const uint32_t aBase = smb + (pass == 2 ? SM_ALO : SM_AHI);
            const uint32_t bBase = smb + (pass == 1 ? SM_BLO : SM_BHI);
#pragma unroll
            for (int ks = 0; ks < 4; ks++) {
                uint32_t a[2][4], b[2][4];
#pragma unroll
                for (int mt = 0; mt < 2; mt++) {
                    uint32_t ad = aBase +
                        (uint32_t)((wm * 32 + mt * 16 + a_row) * (LDA * 2) +
                                   (ks * 16 + a_koff) * 2);
                    ldsm_x4(a[mt][0], a[mt][1], a[mt][2], a[mt][3], ad);
                }
#pragma unroll
                for (int np = 0; np < 2; np++) {
                    uint32_t bd = bBase +
                        (uint32_t)((wn * 32 + np * 16 + b_n) * (LDA * 2) +
                                   (ks * 16 + b_koff) * 2);
                    ldsm_x4(b[np][0], b[np][1], b[np][2], b[np][3], bd);
                }
#pragma unroll
                for (int mt = 0; mt < 2; mt++) {
#pragma unroll
                    for (int np = 0; np < 2; np++) {
                        uint32_t bfr0[2] = { b[np][0], b[np][2] };
                        uint32_t bfr1[2] = { b[np][1], b[np][3] };
                        mma_bf16(acc[mt][2 * np + 0], a[mt], bfr0);
                        mma_bf16(acc[mt][2 * np + 1], a[mt], bfr1);
                    }
                }
            }
        }
        __syncthreads();
    }

    const int r_in = lane >> 2, c_in = (lane & 3) << 1;
#pragma unroll
    for (int mt = 0; mt < 2; mt++) {
        int mrow = m0 + wm * 32 + mt * 16 + r_in;
#pragma unroll
        for (int nt = 0; nt < 4; nt++) {
            int col = n0 + wn * 32 + nt * 8 + c_in;
#pragma unroll
            for (int e = 0; e < 4; e++) {
                int rr = mrow + ((e >> 1) << 3);
                int cc = col + (e & 1);
                if (cc < Nvalid) {
                    float v = acc[mt][nt][e] + bias[cc] + res[(size_t)rr * Nvalid + cc];
                    Cf[(size_t)rr * ldc + cc] = v;
                }
            }
        }
    }
}

// ---------------- conv1 ----------------
__global__ void __launch_bounds__(256) conv1_tc(
    const __nv_bfloat16* __restrict__ xnp,
    const __nv_bfloat16* __restrict__ wh, const __nv_bfloat16* __restrict__ wl,
    const float* __restrict__ bias, __nv_bfloat16* __restrict__ y1p) {
    __shared__ __align__(16) __nv_bfloat16 sA[128 * LDA];
    __shared__ __align__(16) __nv_bfloat16 sBh[64 * LDA];
    __shared__ __align__(16) __nv_bfloat16 sBl[64 * LDA];
    const uint32_t sAu = smem_u32(sA), sBhu = smem_u32(sBh), sBlu = smem_u32(sBl);
    const int tid = threadIdx.x, wid = tid >> 5, lane = tid & 31;
    const int wm = wid >> 1, wn = wid & 1;
    const int tile = blockIdx.x;
    const int r = tile >> 1, c0 = (tile & 1) << 7;
    const int base = (r + 1) * PW + c0 + 1;
    const int a_row = lane & 15, a_koff = (lane >> 4) << 3;
    const int b_grp = lane >> 3, b_n = ((b_grp & 1) << 3) + (lane & 7), b_koff = (b_grp >> 1) << 3;
    float acc[2][4][4] = {};

    for (int tap = 0; tap < 9; tap++) {
        int dy = tap / 3 - 1, dx = tap % 3 - 1;
        int off = dy * PW + dx;
        for (int ch = 0; ch < 3; ch++) {
            __syncthreads();
#pragma unroll
            for (int it = 0; it < 4; it++) {
                int c = tid + it * 256;
                int rr = c >> 3, ko = (c & 7) << 3;
                *(uint4*)(sA + rr * LDA + ko) =
                    *(const uint4*)(xnp + (size_t)(base + off + rr) * KP1 + ch * 64 + ko);
            }
#pragma unroll
            for (int it = 0; it < 2; it++) {
                int c = tid + it * 256;
                int rr = c >> 3, ko = (c & 7) << 3;
                size_t gb = (size_t)(tap * 64 + rr) * KP1 + ch * 64 + ko;
                *(uint4*)(sBh + rr * LDA + ko) = *(const uint4*)(wh + gb);
                *(uint4*)(sBl + rr * LDA + ko) = *(const uint4*)(wl + gb);
            }
            __syncthreads();
#pragma unroll
            for (int pass = 0; pass < 2; pass++) {
                const uint32_t bBase = pass ? sBlu : sBhu;
#pragma unroll
                for (int ks = 0; ks < 4; ks++) {
                    uint32_t a[2][4], b[2][4];
#pragma unroll
                    for (int mt = 0; mt < 2; mt++) {
                        uint32_t ad = sAu +
                            (uint32_t)((wm * 32 + mt * 16 + a_row) * (LDA * 2) +
                                       (ks * 16 + a_koff) * 2);
                        ldsm_x4(a[mt][0], a[mt][1], a[mt][2], a[mt][3], ad);
                    }
#pragma unroll
                    for (int np = 0; np < 2; np++) {
                        uint32_t bd = bBase +
                            (uint32_t)((wn * 32 + np * 16 + b_n) * (LDA * 2) +
                                       (ks * 16 + b_koff) * 2);
                        ldsm_x4(b[np][0], b[np][1], b[np][2], b[np][3], bd);
                    }
#pragma unroll
                    for (int mt = 0; mt < 2; mt++) {
#pragma unroll
                        for (int np = 0; np < 2; np++) {
                            uint32_t bfr0[2] = { b[np][0], b[np][2] };
                            uint32_t bfr1[2] = { b[np][1], b[np][3] };
                            mma_bf16(acc[mt][2 * np + 0], a[mt], bfr0);
                            mma_bf16(acc[mt][2 * np + 1], a[mt], bfr1);
                        }
                    }
                }
            }
        }
    }

    const int r_in = lane >> 2, c_in = (lane & 3) << 1;
#pragma unroll
    for (int mt = 0; mt < 2; mt++) {
        int rowbase = wm * 32 + mt * 16 + r_in;
#pragma unroll
        for (int nt = 0; nt < 4; nt++) {
            int col = wn * 32 + nt * 8 + c_in;
#pragma unroll
            for (int e = 0; e < 4; e++) {
                int rit = rowbase + ((e >> 1) << 3);
                int cc = col + (e & 1);
                float bb = (cc < 60) ? bias[cc] : 0.f;
                float v = gelu_f(acc[mt][nt][e] + bb);
                y1p[(size_t)(base + rit) * 64 + cc] = __float2bfloat16(v);
            }
        }
    }
}

// ---------------- conv2 ----------------
__global__ void __launch_bounds__(256) conv2_tc(
    const __nv_bfloat16* __restrict__ y1p,
    const __nv_bfloat16* __restrict__ wh, const __nv_bfloat16* __restrict__ wl,
    const float* __restrict__ bias, float* __restrict__ y2) {
    __shared__ __align__(16) __nv_bfloat16 sA[128 * LDA];
    __shared__ __align__(16) __nv_bfloat16 sBh[64 * LDA];
    __shared__ __align__(16) __nv_bfloat16 sBl[64 * LDA];
    const uint32_t sAu = smem_u32(sA), sBhu = smem_u32(sBh), sBlu = smem_u32(sBl);
    const int tid = threadIdx.x, wid = tid >> 5, lane = tid & 31;
    const int wm = wid >> 1, wn = wid & 1;
    const int n0 = blockIdx.x * 64;
    const int tile = blockIdx.y;
    const int r = tile >> 1, c0 = (tile & 1) << 7;
    const int base = (r + 1) * PW + c0 + 1;
    const int a_row = lane & 15, a_koff = (lane >> 4) << 3;
    const int b_grp = lane >> 3, b_n = ((b_grp & 1) << 3) + (lane & 7), b_koff = (b_grp >> 1) << 3;
    float acc[2][4][4] = {};

    for (int tap = 0; tap < 9; tap++) {
        int dy = tap / 3 - 1, dx = tap % 3 - 1;
        int off = dy * PW + dx;
        __syncthreads();
#pragma unroll
        for (int it = 0; it < 4; it++) {
            int c = tid + it * 256;
            int rr = c >> 3, ko = (c & 7) << 3;
            *(uint4*)(sA + rr * LDA + ko) =
                *(const uint4*)(y1p + (size_t)(base + off + rr) * 64 + ko);
        }
#pragma unroll
        for (int it = 0; it < 2; it++) {
            int c = tid + it * 256;
            int rr = c >> 3, ko = (c & 7) << 3;
            size_t gb = (size_t)(tap * 192 + n0 + rr) * 64 + ko;
            *(uint4*)(sBh + rr * LDA + ko) = *(const uint4*)(wh + gb);
            *(uint4*)(sBl + rr * LDA + ko) = *(const uint4*)(wl + gb);
        }
        __syncthreads();
#pragma unroll
        for (int pass = 0; pass < 2; pass++) {
            const uint32_t bBase = pass ? sBlu : sBhu;
#pragma unroll
            for (int ks = 0; ks < 4; ks++) {
                uint32_t a[2][4], b[2][4];
#pragma unroll
                for (int mt = 0; mt < 2; mt++) {
                    uint32_t ad = sAu +
                        (uint32_t)((wm * 32 + mt * 16 + a_row) * (LDA * 2) +
                                   (ks * 16 + a_koff) * 2);
                    ldsm_x4(a[mt][0], a[mt][1], a[mt][2], a[mt][3], ad);
                }
#pragma unroll
                for (int np = 0; np < 2; np++) {
                    uint32_t bd = bBase +
                        (uint32_t)((wn * 32 + np * 16 + b_n) * (LDA * 2) +
                                   (ks * 16 + b_koff) * 2);
                    ldsm_x4(b[np][0], b[np][1], b[np][2], b[np][3], bd);
                }
#pragma unroll
                for (int mt = 0; mt < 2; mt++) {
#pragma unroll
                    for (int np = 0; np < 2; np++) {
                        uint32_t bfr0[2] = { b[np][0], b[np][2] };
                        uint32_t bfr1[2] = { b[np][1], b[np][3] };
                        mma_bf16(acc[mt][2 * np + 0], a[mt], bfr0);
                        mma_bf16(acc[mt][2 * np + 1], a[mt], bfr1);
                    }
                }
            }
        }
    }

    const int r_in = lane >> 2, c_in = (lane & 3) << 1;
#pragma unroll
    for (int mt = 0; mt < 2; mt++) {
        int rowbase = wm * 32 + mt * 16 + r_in;
#pragma unroll
        for (int nt = 0; nt < 4; nt++) {
            int col = n0 + wn * 32 + nt * 8 + c_in;
#pragma unroll
            for (int e = 0; e < 4; e++) {
                int rit = rowbase + ((e >> 1) << 3);
                int cc = col + (e & 1);
                if (cc < CDIM) {
                    int p = r * 256 + c0 + rit;
                    y2[(size_t)p * CDIM + cc] = acc[mt][nt][e] + bias[cc];
                }
            }
        }
    }
}

// ---------------- LayerNorm ----------------
__global__ void ln_kernel(const float* __restrict__ x, const float* __restrict__ g,
                          const float* __restrict__ b, float* __restrict__ out,
                          __nv_bfloat16* __restrict__ xnp) {
    int p = blockIdx.x * 8 + (threadIdx.x >> 5);
    int lane = threadIdx.x & 31;
    const float* xr = x + (size_t)p * CDIM;
    float v[6];
    float s = 0.f;
#pragma unroll
    for (int k = 0; k < 6; k++) {
        int c = k * 32 + lane;
        v[k] = (c < CDIM) ? xr[c] : 0.f;
        s += v[k];
    }
    s = warp_sum(s);
    float mu = s * (1.0f / CDIM);
    float sq = 0.f;
#pragma unroll
    for (int k = 0; k < 6; k++) {
        int c = k * 32 + lane;
        if (c < CDIM) { float d = v[k] - mu; sq += d * d; }
    }
    sq = warp_sum(sq);
    float rstd = rsqrtf(sq * (1.0f / CDIM) + 1e-5f);
    float* orow = out + (size_t)p * CDIM;
    int rr = p >> 8, cc = p & 255;
    size_t pidx = (size_t)((rr + 1) * PW + cc + 1) * KP1;
#pragma unroll
    for (int k = 0; k < 6; k++) {
        int c = k * 32 + lane;
        if (c < CDIM) {
            float y = (v[k] - mu) * rstd * g[c] + b[c];
            orow[c] = y;
            xnp[pidx + c] = __float2bfloat16(y);
        }
    }
}

// ---------------- roll + window gather -> bf16 hi/lo A ----------------
__global__ void gather_kernel(const float* __restrict__ xn,
                              __nv_bfloat16* __restrict__ ah, __nv_bfloat16* __restrict__ al) {
    int widx = blockIdx.x;
    int c = threadIdx.x;
    if (c >= CDIM) return;
    int win = widx >> 8, tok = widx & 255;
    int hs = ((win >> 4) << 4) + (tok >> 4);
    int ws2 = ((win & 15) << 4) + (tok & 15);
    int hr = (hs + 8) & 255;
    int wr = (ws2 + 8) & 255;
    float v = xn[(size_t)(hr * 256 + wr) * CDIM + c];
    store_hilo(ah, al, (size_t)widx * KP1 + c, v);
}

// ---------------- bias tables (bf16) ----------------
__global__ void rpb_kernel(const int* __restrict__ rpi, const float* __restrict__ table,
                           __nv_bfloat16* __restrict__ rpb) {
    int idx = blockIdx.x * 256 + threadIdx.x;
    int r = rpi[idx];
#pragma unroll
    for (int h = 0; h < NHEADS; h++)
        rpb[h * 65536 + idx] = __float2bfloat16(table[r * NHEADS + h]);
}
__global__ void maskb_kernel(const float* __restrict__ mask, __nv_bfloat16* __restrict__ mb) {
    size_t i = (size_t)blockIdx.x * 256 + threadIdx.x;
    mb[i] = __float2bfloat16(mask[i]);
}

// ---------------- channel attention ----------------
__global__ void pool_kernel(const float* __restrict__ y2, float* __restrict__ casum) {
    int c = threadIdx.x;
    if (c >= CDIM) return;
    int p0 = blockIdx.x * 256;
    float s = 0.f;
    for (int i = 0; i < 256; i++) s += y2[(size_t)(p0 + i) * CDIM + c];
    atomicAdd(&casum[c], s);
}

__global__ void ca_kernel(const float* __restrict__ casum,
                          const float* __restrict__ w1, const float* __restrict__ b1,
                          const float* __restrict__ w2, const float* __restrict__ b2,
                          float* __restrict__ ca) {
    __shared__ float mean[CDIM];
    __shared__ float sq[6];
    int t = threadIdx.x;
    if (t < CDIM) mean[t] = casum[t] * (1.0f / NP);
    __syncthreads();
    if (t < 6) {
        float a = b1[t];
        for (int c = 0; c < CDIM; c++) a += mean[c] * w1[t * CDIM + c];
        sq[t] = fmaxf(a, 0.f);
    }
    __syncthreads();
    if (t < CDIM) {
        float a = b2[t];
#pragma unroll
        for (int s = 0; s < 6; s++) a += sq[s] * w2[t * 6 + s];
        ca[t] = 1.0f / (1.0f + __expf(-a));
    }
}

// ---------------- flash attention via mma.sync (block = window x head) ----------------
// smem layout (bf16 elements): Qh[256*40], Ql[256*40], Kh[64*40], Kl[64*40],
// Vh[32*72], Vl[32*72]
#define AQ_H 0
#define AQ_L 10240
#define AK_H 20480
#define AK_L 23040
#define AV_H 25600
#define AV_L 27904
#define ATTN_SMEM ((27904 + 32 * 72) * 2)

__global__ void __launch_bounds__(256, 1) attn_mma(
    const float* __restrict__ qkv,
    const __nv_bfloat16* __restrict__ rpbb, const __nv_bfloat16* __restrict__ maskb,
    __nv_bfloat16* __restrict__ oh, __nv_bfloat16* __restrict__ ol) {
    extern __shared__ __align__(16) __nv_bfloat16 smA[];
    const uint32_t smb = smem_u32(smA);
    const int win = blockIdx.x, head = blockIdx.y;
    const int tid = threadIdx.x, w = tid >> 5, lane = tid & 31;
    const int r_in = lane >> 2;
    const int a_row = lane & 15, a_koff = (lane >> 4) << 3;
    const int b_grp = lane >> 3, b_n = ((b_grp & 1) << 3) + (lane & 7), b_koff = (b_grp >> 1) << 3;

    // stage Q (one token per thread), scaled
    {
        const float* qp = qkv + ((size_t)(win * 256 + tid)) * 540 + head * HD;
        __nv_bfloat16* qh = smA + AQ_H + tid * 40;
        __nv_bfloat16* ql = smA + AQ_L + tid * 40;
#pragma unroll
        for (int d = 0; d < 32; d++) {
            float v = (d < HD) ? qp[d] * 0.18257418583505536f : 0.f;
            __nv_bfloat16 h = __float2bfloat16(v);
            qh[d] = h;
            ql[d] = __float2bfloat16(v - __bfloat162float(h));
        }
    }

    float accO[2][4][4] = {};
    float mrow[4] = { -1e30f, -1e30f, -1e30f, -1e30f };
    float lrow[4] = { 0.f, 0.f, 0.f, 0.f };

    const __nv_bfloat16* rbbase = rpbb + (size_t)head * 65536;
    const __nv_bfloat16* mkbase = maskb + (size_t)win * 65536;

    for (int chunk = 0; chunk < 4; chunk++) {
        const int kb = chunk * 64;
        __syncthreads();   // previous chunk's mma done before overwriting K/V
        // stage K chunk [64 keys][32 dims]
        {
            int key = tid >> 2, dg = (tid & 3) * 8;
            const float* kp = qkv + ((size_t)(win * 256 + kb + key)) * 540 + 180 + head * HD;
            __nv_bfloat16* kh = smA + AK_H + key * 40;
            __nv_bfloat16* kl = smA + AK_L + key * 40;
#pragma unroll
            for (int i = 0; i < 8; i++) {
                int d = dg + i;
                float v = (d < HD) ? kp[d] : 0.f;
                __nv_bfloat16 h = __float2bfloat16(v);
                kh[d] = h;
                kl[d] = __float2bfloat16(v - __bfloat162float(h));
            }
        }
        // stage V chunk transposed [32 dims][64 keys]
        {
            int kp2 = (tid & 31) * 2;
            int d0 = tid >> 5;  // 0..7
            const float* vp0 = qkv + ((size_t)(win * 256 + kb + kp2)) * 540 + 360 + head * HD;
            const float* vp1 = vp0 + 540;
#pragma unroll
            for (int it = 0; it < 4; it++) {
                int d = d0 + it * 8;
                float v0 = (d < HD) ? vp0[d] : 0.f;
                float v1 = (d < HD) ? vp1[d] : 0.f;
                __nv_bfloat16 h0 = __float2bfloat16(v0);
                __nv_bfloat16 h1 = __float2bfloat16(v1);
                smA[AV_H + d * 72 + kp2] = h0;
                smA[AV_H + d * 72 + kp2 + 1] = h1;
                smA[AV_L + d * 72 + kp2] = __float2bfloat16(v0 - __bfloat162float(h0));
                smA[AV_L + d * 72 + kp2 + 1] = __float2bfloat16(v1 - __bfloat162float(h1));
            }
        }
        __syncthreads();

        // S = Q K^T (3-pass hi/lo), warp w owns rows 32w..32w+31
        float accS[2][8][4] = {};
#pragma unroll
        for (int pass = 0; pass < 3; pass++) {
            const uint32_t qB = smb + ((pass == 2) ? AQ_L : AQ_H) * 2;
            const uint32_t kB = smb + ((pass == 1) ? AK_L : AK_H) * 2;
#pragma unroll
            for (int kk = 0; kk < 2; kk++) {
                uint32_t a[2][4], b[4][4];
#pragma unroll
                for (int mt = 0; mt < 2; mt++) {
                    uint32_t ad = qB + (uint32_t)((w * 32 + mt * 16 + a_row) * 80 +
                                                  (kk * 16 + a_koff) * 2);
                    ldsm_x4(a[mt][0], a[mt][1], a[mt][2], a[mt][3], ad);
                }
#pragma unroll
                for (int np = 0; np < 4; np++) {
                    uint32_t bd = kB + (uint32_t)((np * 16 + b_n) * 80 +
                                                  (kk * 16 + b_koff) * 2);
                    ldsm_x4(b[np][0], b[np][1], b[np][2], b[np][3], bd);
                }
#pragma unroll
                for (int mt = 0; mt < 2; mt++) {
#pragma unroll
                    for (int np = 0; np < 4; np++) {
                        uint32_t f0[2] = { b[np][0], b[np][2] };
                        uint32_t f1[2] = { b[np][1], b[np][3] };
                        mma_bf16(accS[mt][2 * np + 0], a[mt], f0);
                        mma_bf16(accS[mt][2 * np + 1], a[mt], f1);
                    }
                }
            }
        }

        // add rpb + mask bias
#pragma unroll
        for (int mt = 0; mt < 2; mt++) {
            int r0 = w * 32 + mt * 16 + r_in;
            const __nv_bfloat16* rb0 = rbbase + (size_t)r0 * 256;
            const __nv_bfloat16* rb1 = rb0 + 8 * 256;
            const __nv_bfloat16* mk0 = mkbase + (size_t)r0 * 256;
            const __nv_bfloat16* mk1 = mk0 + 8 * 256;
#pragma unroll
            for (int nt = 0; nt < 8; nt++) {
                int colb = kb + nt * 8 + ((lane & 3) << 1);
                __nv_bfloat162 rA = *(const __nv_bfloat162*)(rb0 + colb);
                __nv_bfloat162 mA = *(const __nv_bfloat162*)(mk0 + colb);
                __nv_bfloat162 rB = *(const __nv_bfloat162*)(rb1 + colb);
                __nv_bfloat162 mB = *(const __nv_bfloat162*)(mk1 + colb);
                accS[mt][nt][0] += __bfloat162float(rA.x) + __bfloat162float(mA.x);
                accS[mt][nt][1] += __bfloat162float(rA.y) + __bfloat162float(mA.y);
                accS[mt][nt][2] += __bfloat162float(rB.x) + __bfloat162float(mB.x);
                accS[mt][nt][3] += __bfloat162float(rB.y) + __bfloat162float(mB.y);
            }
        }

        // online softmax (rows fully in-warp; quad shuffle reduce)
        float corr[4];
#pragma unroll
        for (int s2 = 0; s2 < 4; s2++) {
            int mt = s2 >> 1, h = s2 & 1;
            float mx = -1e30f;
#pragma unroll
            for (int nt = 0; nt < 8; nt++) {
                mx = fmaxf(mx, fmaxf(accS[mt][nt][h * 2], accS[mt][nt][h * 2 + 1]));
            }
            mx = fmaxf(mx, __shfl_xor_sync(0xffffffffu, mx, 1));
            mx = fmaxf(mx, __shfl_xor_sync(0xffffffffu, mx, 2));
            float mnew = fmaxf(mrow[s2], mx);
            corr[s2] = __expf(mrow[s2] - mnew);
            mrow[s2] = mnew;
            float rs = 0.f;
#pragma unroll
            for (int nt = 0; nt < 8; nt++) {
                float p0 = __expf(accS[mt][nt][h * 2] - mnew);
                float p1 = __expf(accS[mt][nt][h * 2 + 1] - mnew);
                accS[mt][nt][h * 2] = p0;
                accS[mt][nt][h * 2 + 1] = p1;
                rs += p0 + p1;
            }
            rs += __shfl_xor_sync(0xffffffffu, rs, 1);
            rs += __shfl_xor_sync(0xffffffffu, rs, 2);
            lrow[s2] = lrow[s2] * corr[s2] + rs;
        }
#pragma unroll
        for (int mt = 0; mt < 2; mt++)
#pragma unroll
            for (int nt = 0; nt < 4; nt++)
#pragma unroll
                for (int e = 0; e < 4; e++)
                    accO[mt][nt][e] *= corr[mt * 2 + (e >> 1)];

        // O += P V (P frags from accS registers; 3-pass hi/lo)
#pragma unroll
        for (int kk = 0; kk < 4; kk++) {
            uint32_t phi[2][4], plo[2][4];
#pragma unroll
            for (int mt = 0; mt < 2; mt++) {
                int nt0 = 2 * kk, nt1 = 2 * kk + 1;
                split2(accS[mt][nt0][0], accS[mt][nt0][1], phi[mt][0], plo[mt][0]);
                split2(accS[mt][nt0][2], accS[mt][nt0][3], phi[mt][1], plo[mt][1]);
                split2(accS[mt][nt1][0], accS[mt][nt1][1], phi[mt][2], plo[mt][2]);
                split2(accS[mt][nt1][2], accS[mt][nt1][3], phi[mt][3], plo[mt][3]);
            }
            uint32_t bh[2][4], bl[2][4];
#pragma unroll
            for (int np = 0; np < 2; np++) {
                uint32_t adh = smb + AV_H * 2 +
                    (uint32_t)((np * 16 + b_n) * 144 + (kk * 16 + b_koff) * 2);
                uint32_t adl = smb + AV_L * 2 +
                    (uint32_t)((np * 16 + b_n) * 144 + (kk * 16 + b_koff) * 2);
                ldsm_x4(bh[np][0], bh[np][1], bh[np][2], bh[np][3], adh);
                ldsm_x4(bl[np][0], bl[np][1], bl[np][2], bl[np][3], adl);
            }
#pragma unroll
            for (int mt = 0; mt < 2; mt++) {
#pragma unroll
                for (int np = 0; np < 2; np++) {
                    uint32_t h0[2] = { bh[np][0], bh[np][2] };
                    uint32_t h1[2] = { bh[np][1], bh[np][3] };
                    uint32_t l0[2] = { bl[np][0], bl[np][2] };
                    uint32_t l1[2] = { bl[np][1], bl[np][3] };
                    mma_bf16(accO[mt][2 * np + 0], phi[mt], h0);
                    mma_bf16(accO[mt][2 * np + 1], phi[mt], h1);
                    mma_bf16(accO[mt][2 * np + 0], plo[mt], h0);
                    mma_bf16(accO[mt][2 * np + 1], plo[mt], h1);
                    mma_bf16(accO[mt][2 * np + 0], phi[mt], l0);
                    mma_bf16(accO[mt][2 * np + 1], phi[mt], l1);
                }
            }
        }
    }

    // write O / l  as hi/lo bf16 into proj input
    float inv[4];
#pragma unroll
    for (int s2 = 0; s2 < 4; s2++) inv[s2] = 1.0f / lrow[s2];
#pragma unroll
    for (int mt = 0; mt < 2; mt++) {
#pragma unroll
        for (int nt = 0; nt < 4; nt++) {
            int dbase = nt * 8 + ((lane & 3) << 1);
#pragma unroll
            for (int e = 0; e < 4; e++) {
                int d = dbase + (e & 1);
                if (d < HD) {
                    int row = w * 32 + mt * 16 + r_in + ((e >> 1) << 3);
                    float v = accO[mt][nt][e] * inv[mt * 2 + (e >> 1)];
                    store_hilo(oh, ol, (size_t)(win * 256 + row) * KP1 + head * HD + d, v);
                }
            }
        }
    }
}

// ---------------- residual combine + LN2 ----------------
__global__ void combine_ln2(const float* __restrict__ x, const float* __restrict__ proj,
                            const float* __restrict__ y2, const float* __restrict__ ca,
                            const float* __restrict__ g2, const float* __restrict__ b2,
                            float* __restrict__ x1,
                            __nv_bfloat16* __restrict__ mh, __nv_bfloat16* __restrict__ ml) {
    int p = blockIdx.x * 8 + (threadIdx.x >> 5);
    int lane = threadIdx.x & 31;
    int r = p >> 8, cc = p & 255;
    int hs = (r + 248) & 255;
    int ws2 = (cc + 248) & 255;
    int widx = (((hs >> 4) << 4) + (ws2 >> 4)) * 256 + ((hs & 15) << 4) + (ws2 & 15);
    float v[6];
    float s = 0.f;
#pragma unroll
    for (int k = 0; k < 6; k++) {
        int c = k * 32 + lane;
        if (c < CDIM) {
            v[k] = x[(size_t)p * CDIM + c] + proj[(size_t)widx * CDIM + c]
                 + 0.01f * y2[(size_t)p * CDIM + c] * ca[c];
        } else v[k] = 0.f;
        s += v[k];
    }
    s = warp_sum(s);
    float mu = s * (1.0f / CDIM);
    float sq = 0.f;
#pragma unroll
    for (int k = 0; k < 6; k++) {
        int c = k * 32 + lane;
        if (c < CDIM) { float d = v[k] - mu; sq += d * d; }
    }
    sq = warp_sum(sq);
    float rstd = rsqrtf(sq * (1.0f / CDIM) + 1e-5f);
#pragma unroll
    for (int k = 0; k < 6; k++) {
        int c = k * 32 + lane;
        if (c < CDIM) {
            x1[(size_t)p * CDIM + c] = v[k];
            store_hilo(mh, ml, (size_t)p * KP1 + c, (v[k] - mu) * rstd * g2[c] + b2[c]);
        }
    }
}

// ---------------- launcher ----------------
extern "C" void kernel_launch(void* const* d_in, const int* in_sizes, int n_in,
                              void* d_out, int out_size) {
    const float* x     = (const float*)d_in[0];
    const int*   rpi   = (const int*)d_in[3];
    const float* mask  = (const float*)d_in[4];
    const float* n1g   = (const float*)d_in[5];
    const float* n1b   = (const float*)d_in[6];
    const float* qkvw  = (const float*)d_in[7];
    const float* qkvb  = (const float*)d_in[8];
    const float* rpbt  = (const float*)d_in[9];
    const float* projw = (const float*)d_in[10];
    const float* projb = (const float*)d_in[11];
    const float* c1w   = (const float*)d_in[12];
    const float* c1b   = (const float*)d_in[13];
    const float* c2w   = (const float*)d_in[14];
    const float* c2b   = (const float*)d_in[15];
    const float* ca1w  = (const float*)d_in[16];
    const float* ca1b  = (const float*)d_in[17];
    const float* ca2w  = (const float*)d_in[18];
    const float* ca2b  = (const float*)d_in[19];
    const float* n2g   = (const float*)d_in[20];
    const float* n2b   = (const float*)d_in[21];
    const float* f1w   = (const float*)d_in[22];
    const float* f1b   = (const float*)d_in[23];
    const float* f2w   = (const float*)d_in[24];
    const float* f2b   = (const float*)d_in[25];
    float* out = (float*)d_out;

    float *xn, *qkv, *proj, *y2, *casum, *ca, *x1;
    __nv_bfloat16 *rpbb, *maskb;
    __nv_bfloat16 *xnp, *y1p, *ahi, *alo, *mhi, *mlo;
    __nv_bfloat16 *bqh, *bql, *bph, *bpl, *b1h, *b1l, *b2h, *b2l;
    __nv_bfloat16 *wc1h, *wc1l, *wc2h, *wc2l;
    cudaGetSymbolAddress((void**)&xn, g_xn);
    cudaGetSymbolAddress((void**)&qkv, g_qkv);
    cudaGetSymbolAddress((void**)&proj, g_proj);
    cudaGetSymbolAddress((void**)&y2, g_y2);
    cudaGetSymbolAddress((void**)&rpbb, g_rpbb);
    cudaGetSymbolAddress((void**)&maskb, g_maskb);
    cudaGetSymbolAddress((void**)&casum, g_casum);
    cudaGetSymbolAddress((void**)&ca, g_ca);
    cudaGetSymbolAddress((void**)&x1, g_x1);
    cudaGetSymbolAddress((void**)&xnp, g_xnp);
    cudaGetSymbolAddress((void**)&y1p, g_y1p);
    cudaGetSymbolAddress((void**)&ahi, g_ahi);
    cudaGetSymbolAddress((void**)&alo, g_alo);
    cudaGetSymbolAddress((void**)&mhi, g_mhi);
    cudaGetSymbolAddress((void**)&mlo, g_mlo);
    cudaGetSymbolAddress((void**)&bqh, g_bqh);
    cudaGetSymbolAddress((void**)&bql, g_bql);
    cudaGetSymbolAddress((void**)&bph, g_bph);
    cudaGetSymbolAddress((void**)&bpl, g_bpl);
    cudaGetSymbolAddress((void**)&b1h, g_b1h);
    cudaGetSymbolAddress((void**)&b1l, g_b1l);
    cudaGetSymbolAddress((void**)&b2h, g_b2h);
    cudaGetSymbolAddress((void**)&b2l, g_b2l);
    cudaGetSymbolAddress((void**)&wc1h, g_wc1h);
    cudaGetSymbolAddress((void**)&wc1l, g_wc1l);
    cudaGetSymbolAddress((void**)&wc2h, g_wc2h);
    cudaGetSymbolAddress((void**)&wc2l, g_wc2l);

    cudaFuncSetAttribute(tc_gemm2<0>, cudaFuncAttributeMaxDynamicSharedMemorySize, G2_SMEM);
    cudaFuncSetAttribute(tc_gemm2<1>, cudaFuncAttributeMaxDynamicSharedMemorySize, G2_SMEM);
    cudaFuncSetAttribute(tc_gemm_res, cudaFuncAttributeMaxDynamicSharedMemorySize, TC_SMEM_BYTES);
    cudaFuncSetAttribute(attn_mma, cudaFuncAttributeMaxDynamicSharedMemorySize, ATTN_SMEM);

    // weight prep (tiny)
    prepb_kernel<<<432, 256>>>(qkvw, 180, 540, KP1, 576, bqh, bql);
    prepb_kernel<<<144, 256>>>(projw, 180, 180, KP1, 192, bph, bpl);
    prepb_kernel<<<576, 256>>>(f1w, 180, 720, KP1, 768, b1h, b1l);
    prepb_kernel<<<576, 256>>>(f2w, 720, 180, KP2, 192, b2h, b2l);
    prepc1_kernel<<<432, 256>>>(c1w, wc1h, wc1l);
    prepc2_kernel<<<432, 256>>>(c2w, wc2h, wc2l);

    ln_kernel<<<NP / 8, 256>>>(x, n1g, n1b, xn, xnp);
    gather_kernel<<<NP, 192>>>(xn, ahi, alo);
    rpb_kernel<<<256, 256>>>(rpi, rpbt, rpbb);
    maskb_kernel<<<65536, 256>>>(mask, maskb);

    // qkv projection + attention + proj
    tc_gemm2<0><<<512, 256, G2_SMEM>>>(ahi, alo, bqh, bql, qkvb, qkv, nullptr, nullptr,
                                       540, 540, 9);
    attn_mma<<<dim3(256, 6), 256, ATTN_SMEM>>>(qkv, rpbb, maskb, ahi, alo);
    tc_gemm2<0><<<512, 256, G2_SMEM>>>(ahi, alo, bph, bpl, projb, proj, nullptr, nullptr,
                                       180, 180, 3);

    // conv branch
    conv1_tc<<<512, 256>>>(xnp, wc1h, wc1l, c1b, y1p);
    conv2_tc<<<dim3(3, 512), 256>>>(y1p, wc2h, wc2l, c2b, y2);
    cudaMemsetAsync(casum, 0, CDIM * sizeof(float));
    pool_kernel<<<256, 192>>>(y2, casum);
    ca_kernel<<<1, 192>>>(casum, ca1w, ca1b, ca2w, ca2b, ca);

    // combine + LN2 + MLP
    combine_ln2<<<NP / 8, 256>>>(x, proj, y2, ca, n2g, n2b, x1, ahi, alo);
    tc_gemm2<1><<<512, 256, G2_SMEM>>>(ahi, alo, b1h, b1l, f1b, nullptr, mhi, mlo,
                                       720, 768, 12);
    tc_gemm_res<<<dim3(3, 512), 256, TC_SMEM_BYTES>>>(mhi, mlo, b2h, b2l, f2b, x1, out,
                                                      180, 180, KP2, 12);
}